// round 1
// baseline (speedup 1.0000x reference)
#include <cuda_runtime.h>
#include <math.h>
#include <stddef.h>

// Problem dims
#define BV 7800
#define DD 300
#define RR 512
#define HH 512
#define FEAT 2048
#define BB 128
#define AA 196
#define TT 20           // T-1 steps
#define A1 197          // A+1 (sentinel + regions)
#define G5 2560         // 5*R
#define MROWS 25088     // B*A
#define OUT_ROW 156000  // TT*BV (per-b stride in output)

// ---------------- device scratch ----------------
__device__ float g_v[MROWS * RR];        // relu(att @ ae_W^T + b)     [25088,512]
__device__ float g_vemb[MROWS * RR];     // v @ c2a_W^T + b            [25088,512]
__device__ float g_xall[TT * BB * DD];   // relu(E[tok]) for all steps [2560,300]
__device__ float g_gx[TT * BB * G5];     // xt @ w_ih^T for all steps  [2560,2560]
__device__ float g_gates[BB * G5];
__device__ float g_h[BB * RR];
__device__ float g_c[BB * RR];
__device__ float g_sent[BB * RR];
__device__ float g_sentemb[BB * HH];
__device__ float g_hemb[BB * HH];
__device__ float g_x2[BB * RR];          // cHat + hy
__device__ float g_hout[BB * RR];
__device__ float g_alpha[BB * A1];

// ---------------- helpers ----------------
__device__ __forceinline__ float sigmoidf_(float x) { return 1.0f / (1.0f + expf(-x)); }

// ---------------- init ----------------
__global__ void init_state_kernel(float* h, float* c) {
    int i = blockIdx.x * blockDim.x + threadIdx.x;
    if (i < BB * RR) { h[i] = 0.0f; c[i] = 0.0f; }
}

// xall[(t*128+b)*300 + d] = relu(E[seq[b*21+t]*300 + d])
__global__ void embed_all_kernel(const int* __restrict__ seq, const float* __restrict__ E,
                                 float* __restrict__ xall) {
    int idx = blockIdx.x * blockDim.x + threadIdx.x;
    if (idx >= TT * BB * DD) return;
    int d = idx % DD;
    int row = idx / DD;
    int t = row / BB;
    int b = row % BB;
    int tok = seq[b * 21 + t];
    float v = E[(size_t)tok * DD + d];
    xall[idx] = fmaxf(v, 0.0f);
}

// ---------------- big SGEMM: C[M,N] = act(A[M,K] @ W[N,K]^T + bias) ----------------
// BM=BN=128, BK=8, 256 threads, 8x8 microtile. M%128==0, N%128==0, K%8==0.
template <bool RELU>
__global__ void __launch_bounds__(256) sgemm_big(const float* __restrict__ A,
                                                 const float* __restrict__ W,
                                                 const float* __restrict__ bias,
                                                 float* __restrict__ C,
                                                 int M, int N, int K) {
    __shared__ float As[8][128];
    __shared__ float Bs[8][128];
    int bm = blockIdx.x * 128, bn = blockIdx.y * 128;
    int tid = threadIdx.x;
    int tx = tid & 15, ty = tid >> 4;
    int lr = tid >> 1;
    int lk = (tid & 1) * 4;
    const float* Aptr = A + (size_t)(bm + lr) * K + lk;
    const float* Wptr = W + (size_t)(bn + lr) * K + lk;
    float acc[8][8];
#pragma unroll
    for (int i = 0; i < 8; i++)
#pragma unroll
        for (int j = 0; j < 8; j++) acc[i][j] = 0.0f;

    for (int k0 = 0; k0 < K; k0 += 8) {
        float4 a4 = *(const float4*)(Aptr + k0);
        float4 b4 = *(const float4*)(Wptr + k0);
        As[lk + 0][lr] = a4.x; As[lk + 1][lr] = a4.y;
        As[lk + 2][lr] = a4.z; As[lk + 3][lr] = a4.w;
        Bs[lk + 0][lr] = b4.x; Bs[lk + 1][lr] = b4.y;
        Bs[lk + 2][lr] = b4.z; Bs[lk + 3][lr] = b4.w;
        __syncthreads();
#pragma unroll
        for (int k = 0; k < 8; k++) {
            float ra[8], rb[8];
#pragma unroll
            for (int i = 0; i < 8; i++) ra[i] = As[k][ty * 8 + i];
#pragma unroll
            for (int j = 0; j < 8; j++) rb[j] = Bs[k][tx * 8 + j];
#pragma unroll
            for (int i = 0; i < 8; i++)
#pragma unroll
                for (int j = 0; j < 8; j++) acc[i][j] += ra[i] * rb[j];
        }
        __syncthreads();
    }
#pragma unroll
    for (int i = 0; i < 8; i++) {
        int m = bm + ty * 8 + i;
#pragma unroll
        for (int j = 0; j < 8; j++) {
            int n = bn + tx * 8 + j;
            float v = acc[i][j] + bias[n];
            if (RELU) v = fmaxf(v, 0.0f);
            C[(size_t)m * N + n] = v;
        }
    }
}

// ---------------- small-M SGEMM ----------------
// C[m*ldc+n] = act( A@W^T + Cin[m*ldcin+n] + bias[n] ), guards on n<N and k<K.
// BM=BN=64, BK=16, 256 threads, 4x4 microtile. M%64==0.
template <int ACT>  // 0 none, 1 tanh
__global__ void __launch_bounds__(256) sgemm_small(const float* __restrict__ A,
                                                   const float* __restrict__ W,
                                                   const float* __restrict__ bias,
                                                   const float* __restrict__ Cin,
                                                   float* __restrict__ C,
                                                   int M, int N, int K,
                                                   int ldc, int ldcin) {
    __shared__ float As[16][64];
    __shared__ float Bs[16][64];
    int bm = blockIdx.x * 64, bn = blockIdx.y * 64;
    int tid = threadIdx.x;
    int tx = tid & 15, ty = tid >> 4;
    int lr = tid >> 2;          // 0..63
    int lk = (tid & 3) * 4;     // 0,4,8,12
    float acc[4][4];
#pragma unroll
    for (int i = 0; i < 4; i++)
#pragma unroll
        for (int j = 0; j < 4; j++) acc[i][j] = 0.0f;

    int nload = bn + lr;
    bool nok = (nload < N);
    for (int k0 = 0; k0 < K; k0 += 16) {
#pragma unroll
        for (int i = 0; i < 4; i++) {
            int k = k0 + lk + i;
            As[lk + i][lr] = (k < K) ? A[(size_t)(bm + lr) * K + k] : 0.0f;
            Bs[lk + i][lr] = (k < K && nok) ? W[(size_t)nload * K + k] : 0.0f;
        }
        __syncthreads();
#pragma unroll
        for (int k = 0; k < 16; k++) {
            float ra[4], rb[4];
#pragma unroll
            for (int i = 0; i < 4; i++) ra[i] = As[k][ty * 4 + i];
#pragma unroll
            for (int j = 0; j < 4; j++) rb[j] = Bs[k][tx * 4 + j];
#pragma unroll
            for (int i = 0; i < 4; i++)
#pragma unroll
                for (int j = 0; j < 4; j++) acc[i][j] += ra[i] * rb[j];
        }
        __syncthreads();
    }
#pragma unroll
    for (int i = 0; i < 4; i++) {
        int m = bm + ty * 4 + i;
#pragma unroll
        for (int j = 0; j < 4; j++) {
            int n = bn + tx * 4 + j;
            if (n < N) {
                float v = acc[i][j];
                if (Cin) v += Cin[(size_t)m * ldcin + n];
                if (bias) v += bias[n];
                if (ACT == 1) v = tanhf(v);
                C[(size_t)m * ldc + n] = v;
            }
        }
    }
}

// ---------------- LSTM pointwise ----------------
__global__ void lstm_kernel(const float* __restrict__ gates, float* __restrict__ c,
                            float* __restrict__ h, float* __restrict__ sent) {
    int idx = blockIdx.x * blockDim.x + threadIdx.x;
    if (idx >= BB * RR) return;
    int b = idx / RR, r = idx % RR;
    const float* g = gates + (size_t)b * G5;
    float ig = sigmoidf_(g[r]);
    float fg = sigmoidf_(g[RR + r]);
    float gg = tanhf(g[2 * RR + r]);
    float og = sigmoidf_(g[3 * RR + r]);
    float sg = sigmoidf_(g[4 * RR + r]);
    float cy = tanhf(fg * c[idx] + ig * gg);
    c[idx] = cy;
    sent[idx] = sg * cy;
    h[idx] = og * cy;
}

// ---------------- attention scores + softmax ----------------
__global__ void __launch_bounds__(256) attn_kernel(const float* __restrict__ sentemb,
                                                   const float* __restrict__ hemb,
                                                   const float* __restrict__ vemb,
                                                   const float* __restrict__ alW,
                                                   const float* __restrict__ alb,
                                                   float* __restrict__ alpha) {
    int b = blockIdx.x;
    int tid = threadIdx.x;
    __shared__ float sAl[HH];
    __shared__ float sH[HH];
    __shared__ float sSc[224];
    __shared__ float red[256];
    for (int j = tid; j < HH; j += 256) {
        sAl[j] = alW[j];
        sH[j] = hemb[(size_t)b * HH + j];
    }
    __syncthreads();
    int warp = tid >> 5, lane = tid & 31;
    float ab = alb[0];
    for (int a = warp; a < A1; a += 8) {
        const float* e = (a == 0) ? (sentemb + (size_t)b * HH)
                                  : (vemb + ((size_t)b * AA + (a - 1)) * HH);
        float s = 0.0f;
        for (int j = lane; j < HH; j += 32) s += sAl[j] * tanhf(e[j] + sH[j]);
#pragma unroll
        for (int o = 16; o > 0; o >>= 1) s += __shfl_down_sync(0xffffffffu, s, o);
        if (lane == 0) sSc[a] = s + ab;
    }
    __syncthreads();
    float m = -INFINITY;
    for (int a = tid; a < A1; a += 256) m = fmaxf(m, sSc[a]);
    red[tid] = m; __syncthreads();
    for (int st = 128; st > 0; st >>= 1) {
        if (tid < st) red[tid] = fmaxf(red[tid], red[tid + st]);
        __syncthreads();
    }
    float mx = red[0]; __syncthreads();
    float sum = 0.0f;
    for (int a = tid; a < A1; a += 256) sum += expf(sSc[a] - mx);
    red[tid] = sum; __syncthreads();
    for (int st = 128; st > 0; st >>= 1) {
        if (tid < st) red[tid] += red[tid + st];
        __syncthreads();
    }
    float inv = 1.0f / red[0];
    for (int a = tid; a < A1; a += 256)
        alpha[(size_t)b * A1 + a] = expf(sSc[a] - mx) * inv;
}

// ---------------- cHat + hy ----------------
__global__ void __launch_bounds__(256) chat_kernel(const float* __restrict__ alpha,
                                                   const float* __restrict__ sent,
                                                   const float* __restrict__ v,
                                                   const float* __restrict__ h,
                                                   float* __restrict__ x2) {
    int b = blockIdx.x;
    int r = blockIdx.y * 256 + threadIdx.x;  // 0..511
    __shared__ float sA[A1];
    for (int a = threadIdx.x; a < A1; a += 256) sA[a] = alpha[(size_t)b * A1 + a];
    __syncthreads();
    float acc = sA[0] * sent[(size_t)b * RR + r];
    const float* vp = v + (size_t)b * AA * RR + r;
    for (int a = 0; a < AA; a++) acc += sA[a + 1] * vp[(size_t)a * RR];
    x2[(size_t)b * RR + r] = acc + h[(size_t)b * RR + r];
}

// ---------------- log-softmax in place ----------------
__global__ void __launch_bounds__(256) logsm_kernel(float* __restrict__ base) {
    int b = blockIdx.x;
    float* p = base + (size_t)b * OUT_ROW;
    __shared__ float red[256];
    int tid = threadIdx.x;
    float m = -INFINITY;
    for (int i = tid; i < BV; i += 256) m = fmaxf(m, p[i]);
    red[tid] = m; __syncthreads();
    for (int st = 128; st > 0; st >>= 1) {
        if (tid < st) red[tid] = fmaxf(red[tid], red[tid + st]);
        __syncthreads();
    }
    float mx = red[0]; __syncthreads();
    float sum = 0.0f;
    for (int i = tid; i < BV; i += 256) sum += expf(p[i] - mx);
    red[tid] = sum; __syncthreads();
    for (int st = 128; st > 0; st >>= 1) {
        if (tid < st) red[tid] += red[tid + st];
        __syncthreads();
    }
    float lse = mx + logf(red[0]);
    for (int i = tid; i < BV; i += 256) p[i] -= lse;
}

// ---------------- launch ----------------
extern "C" void kernel_launch(void* const* d_in, const int* in_sizes, int n_in,
                              void* d_out, int out_size) {
    const float* att  = (const float*)d_in[0];
    const int*   seq  = (const int*)d_in[1];
    const float* E    = (const float*)d_in[2];
    const float* w_ih = (const float*)d_in[3];
    const float* w_hh = (const float*)d_in[4];
    const float* aeW  = (const float*)d_in[5];
    const float* aeb  = (const float*)d_in[6];
    const float* c2aW = (const float*)d_in[7];
    const float* c2ab = (const float*)d_in[8];
    const float* seW  = (const float*)d_in[9];
    const float* seb  = (const float*)d_in[10];
    const float* hoW  = (const float*)d_in[11];
    const float* hob  = (const float*)d_in[12];
    const float* alW  = (const float*)d_in[13];
    const float* alb  = (const float*)d_in[14];
    const float* a2hW = (const float*)d_in[15];
    const float* a2hb = (const float*)d_in[16];
    const float* lgW  = (const float*)d_in[17];
    const float* lgb  = (const float*)d_in[18];
    float* out = (float*)d_out;

    float *v, *vemb, *xall, *gx, *gates, *h, *c, *sent, *sentemb, *hemb, *x2, *hout, *alpha;
    cudaGetSymbolAddress((void**)&v, g_v);
    cudaGetSymbolAddress((void**)&vemb, g_vemb);
    cudaGetSymbolAddress((void**)&xall, g_xall);
    cudaGetSymbolAddress((void**)&gx, g_gx);
    cudaGetSymbolAddress((void**)&gates, g_gates);
    cudaGetSymbolAddress((void**)&h, g_h);
    cudaGetSymbolAddress((void**)&c, g_c);
    cudaGetSymbolAddress((void**)&sent, g_sent);
    cudaGetSymbolAddress((void**)&sentemb, g_sentemb);
    cudaGetSymbolAddress((void**)&hemb, g_hemb);
    cudaGetSymbolAddress((void**)&x2, g_x2);
    cudaGetSymbolAddress((void**)&hout, g_hout);
    cudaGetSymbolAddress((void**)&alpha, g_alpha);

    // Hoisted work
    init_state_kernel<<<(BB * RR + 255) / 256, 256>>>(h, c);
    embed_all_kernel<<<(TT * BB * DD + 255) / 256, 256>>>(seq, E, xall);
    sgemm_big<true><<<dim3(MROWS / 128, RR / 128), 256>>>(att, aeW, aeb, v, MROWS, RR, FEAT);
    sgemm_big<false><<<dim3(MROWS / 128, RR / 128), 256>>>(v, c2aW, c2ab, vemb, MROWS, RR, RR);
    // gates_x for all steps: [2560,2560] = xall[2560,300] @ w_ih^T
    sgemm_small<0><<<dim3(TT * BB / 64, G5 / 64), 256>>>(xall, w_ih, nullptr, nullptr, gx,
                                                         TT * BB, G5, DD, G5, 0);

    for (int t = 0; t < TT; t++) {
        // gates = gx[t] + h @ w_hh^T
        sgemm_small<0><<<dim3(BB / 64, G5 / 64), 256>>>(h, w_hh, nullptr,
                                                        gx + (size_t)t * BB * G5, gates,
                                                        BB, G5, RR, G5, G5);
        lstm_kernel<<<(BB * RR + 255) / 256, 256>>>(gates, c, h, sent);
        sgemm_small<0><<<dim3(BB / 64, HH / 64), 256>>>(sent, seW, seb, nullptr, sentemb,
                                                        BB, HH, RR, HH, 0);
        sgemm_small<0><<<dim3(BB / 64, HH / 64), 256>>>(h, hoW, hob, nullptr, hemb,
                                                        BB, HH, RR, HH, 0);
        attn_kernel<<<BB, 256>>>(sentemb, hemb, vemb, alW, alb, alpha);
        chat_kernel<<<dim3(BB, RR / 256), 256>>>(alpha, sent, v, h, x2);
        sgemm_small<1><<<dim3(BB / 64, HH / 64), 256>>>(x2, a2hW, a2hb, nullptr, hout,
                                                        BB, RR, RR, RR, 0);
        sgemm_small<0><<<dim3(BB / 64, (BV + 63) / 64), 256>>>(hout, lgW, lgb, nullptr,
                                                               out + (size_t)t * BV,
                                                               BB, BV, RR, OUT_ROW, 0);
        logsm_kernel<<<BB, 256>>>(out + (size_t)t * BV);
    }
}

// round 2
// speedup vs baseline: 1.2743x; 1.2743x over previous
#include <cuda_runtime.h>
#include <math.h>
#include <stddef.h>

// Problem dims
#define BV 7800
#define DD 300
#define DP 304          // padded D for alignment
#define RR 512
#define HH 512
#define FEAT 2048
#define BB 128
#define AA 196
#define TT 20           // T-1 steps
#define A1 197          // A+1 (sentinel + regions)
#define G5 2560         // 5*R
#define MROWS 25088     // B*A
#define OUT_ROW 156000  // TT*BV (per-b stride in output)

// ---------------- device scratch ----------------
__device__ float g_v[MROWS * RR];        // relu(att @ ae_W^T + b)     [25088,512]
__device__ float g_vemb[MROWS * RR];     // v @ c2a_W^T + b            [25088,512]
__device__ float g_xall[TT * BB * DP];   // relu(E[tok]) padded        [2560,304]
__device__ float g_wihp[G5 * DP];        // padded w_ih                [2560,304]
__device__ float g_gx[TT * BB * G5];     // xt @ w_ih^T for all steps  [2560,2560]
__device__ float g_gates[BB * G5];
__device__ float g_h[BB * RR];
__device__ float g_c[BB * RR];
__device__ float g_sent[BB * RR];
__device__ float g_sentemb[BB * HH];
__device__ float g_hemb[BB * HH];
__device__ float g_x2[BB * RR];          // cHat + hy
__device__ float g_hout[BB * RR];

// ---------------- helpers ----------------
__device__ __forceinline__ float sigmoidf_(float x) { return 1.0f / (1.0f + expf(-x)); }
__device__ __forceinline__ float tanh_fast(float x) {
    float y;
    asm("tanh.approx.f32 %0, %1;" : "=f"(y) : "f"(x));
    return y;
}

// ---------------- init ----------------
__global__ void init_state_kernel(float* h, float* c) {
    int i = blockIdx.x * blockDim.x + threadIdx.x;
    if (i < BB * RR) { h[i] = 0.0f; c[i] = 0.0f; }
}

// wihp[r, c] = (c<300) ? w_ih[r, c] : 0
__global__ void pad_wih_kernel(const float* __restrict__ w, float* __restrict__ wp) {
    int idx = blockIdx.x * blockDim.x + threadIdx.x;
    if (idx >= G5 * DP) return;
    int r = idx / DP, cidx = idx % DP;
    wp[idx] = (cidx < DD) ? w[r * DD + cidx] : 0.0f;
}

// xall[(t*128+b)*304 + d] = relu(E[seq[b*21+t]*300 + d]), zero pad d>=300
__global__ void embed_all_kernel(const int* __restrict__ seq, const float* __restrict__ E,
                                 float* __restrict__ xall) {
    int idx = blockIdx.x * blockDim.x + threadIdx.x;
    if (idx >= TT * BB * DP) return;
    int d = idx % DP;
    int row = idx / DP;
    int t = row / BB;
    int b = row % BB;
    float v = 0.0f;
    if (d < DD) {
        int tok = seq[b * 21 + t];
        v = fmaxf(E[(size_t)tok * DD + d], 0.0f);
    }
    xall[idx] = v;
}

// ---------------- big SGEMM: C[M,N] = act(A[M,K] @ W[N,K]^T + bias) ----------------
// BM=BN=128, BK=8, 256 threads, 8x8 microtile. M%128==0, N%128==0, K%8==0.
template <bool RELU>
__global__ void __launch_bounds__(256) sgemm_big(const float* __restrict__ A,
                                                 const float* __restrict__ W,
                                                 const float* __restrict__ bias,
                                                 float* __restrict__ C,
                                                 int M, int N, int K) {
    __shared__ float As[8][128];
    __shared__ float Bs[8][128];
    int bm = blockIdx.x * 128, bn = blockIdx.y * 128;
    int tid = threadIdx.x;
    int tx = tid & 15, ty = tid >> 4;
    int lr = tid >> 1;
    int lk = (tid & 1) * 4;
    const float* Aptr = A + (size_t)(bm + lr) * K + lk;
    const float* Wptr = W + (size_t)(bn + lr) * K + lk;
    float acc[8][8];
#pragma unroll
    for (int i = 0; i < 8; i++)
#pragma unroll
        for (int j = 0; j < 8; j++) acc[i][j] = 0.0f;

    for (int k0 = 0; k0 < K; k0 += 8) {
        float4 a4 = *(const float4*)(Aptr + k0);
        float4 b4 = *(const float4*)(Wptr + k0);
        As[lk + 0][lr] = a4.x; As[lk + 1][lr] = a4.y;
        As[lk + 2][lr] = a4.z; As[lk + 3][lr] = a4.w;
        Bs[lk + 0][lr] = b4.x; Bs[lk + 1][lr] = b4.y;
        Bs[lk + 2][lr] = b4.z; Bs[lk + 3][lr] = b4.w;
        __syncthreads();
#pragma unroll
        for (int k = 0; k < 8; k++) {
            float ra[8], rb[8];
#pragma unroll
            for (int i = 0; i < 8; i++) ra[i] = As[k][ty * 8 + i];
#pragma unroll
            for (int j = 0; j < 8; j++) rb[j] = Bs[k][tx * 8 + j];
#pragma unroll
            for (int i = 0; i < 8; i++)
#pragma unroll
                for (int j = 0; j < 8; j++) acc[i][j] += ra[i] * rb[j];
        }
        __syncthreads();
    }
#pragma unroll
    for (int i = 0; i < 8; i++) {
        int m = bm + ty * 8 + i;
#pragma unroll
        for (int j = 0; j < 8; j++) {
            int n = bn + tx * 8 + j;
            float v = acc[i][j] + bias[n];
            if (RELU) v = fmaxf(v, 0.0f);
            C[(size_t)m * N + n] = v;
        }
    }
}

// ---------------- mid SGEMM (high-CTA-count, small-M friendly) ----------------
// BM=BN=64, BK=16, 256 threads, 4x4 microtile.
// Requires: M%64==0 (grid covers M), K%16==0, A/W rows 16B-aligned (K%4==0).
// N arbitrary (guarded). C[m*ldc+n] = act(A@W^T + bias[n] + Cin[m*ldcin+n]).
struct MidSmem {
    float As[16][64];
    float Bs[16][64];
};

template <int ACT>  // 0 none, 1 tanh
__device__ __forceinline__ void gemm_mid_body(MidSmem& s,
                                              const float* __restrict__ A,
                                              const float* __restrict__ W,
                                              const float* __restrict__ bias,
                                              const float* __restrict__ Cin,
                                              float* __restrict__ C,
                                              int N, int K, int ldc, int ldcin,
                                              int bm, int bn) {
    int tid = threadIdx.x;
    int lr = tid & 63;
    int lk = (tid >> 6) * 4;  // 0,4,8,12
    int tx = tid & 15, ty = tid >> 4;
    const float* Aptr = A + (size_t)(bm + lr) * K + lk;
    int wn = bn + lr;
    bool wok = (wn < N);
    const float* Wptr = W + (size_t)(wok ? wn : 0) * K + lk;

    float acc[4][4];
#pragma unroll
    for (int i = 0; i < 4; i++)
#pragma unroll
        for (int j = 0; j < 4; j++) acc[i][j] = 0.0f;

    for (int k0 = 0; k0 < K; k0 += 16) {
        float4 a4 = *(const float4*)(Aptr + k0);
        float4 b4 = wok ? *(const float4*)(Wptr + k0) : make_float4(0.f, 0.f, 0.f, 0.f);
        __syncthreads();
        s.As[lk + 0][lr] = a4.x; s.As[lk + 1][lr] = a4.y;
        s.As[lk + 2][lr] = a4.z; s.As[lk + 3][lr] = a4.w;
        s.Bs[lk + 0][lr] = b4.x; s.Bs[lk + 1][lr] = b4.y;
        s.Bs[lk + 2][lr] = b4.z; s.Bs[lk + 3][lr] = b4.w;
        __syncthreads();
#pragma unroll
        for (int k = 0; k < 16; k++) {
            float ra[4], rb[4];
#pragma unroll
            for (int i = 0; i < 4; i++) ra[i] = s.As[k][ty * 4 + i];
#pragma unroll
            for (int j = 0; j < 4; j++) rb[j] = s.Bs[k][tx * 4 + j];
#pragma unroll
            for (int i = 0; i < 4; i++)
#pragma unroll
                for (int j = 0; j < 4; j++) acc[i][j] += ra[i] * rb[j];
        }
    }
#pragma unroll
    for (int i = 0; i < 4; i++) {
        int m = bm + ty * 4 + i;
#pragma unroll
        for (int j = 0; j < 4; j++) {
            int n = bn + tx * 4 + j;
            if (n < N) {
                float v = acc[i][j];
                if (bias) v += bias[n];
                if (Cin) v += Cin[(size_t)m * ldcin + n];
                if (ACT == 1) v = tanhf(v);
                C[(size_t)m * ldc + n] = v;
            }
        }
    }
}

template <int ACT>
__global__ void __launch_bounds__(256) sgemm_mid(const float* __restrict__ A,
                                                 const float* __restrict__ W,
                                                 const float* __restrict__ bias,
                                                 const float* __restrict__ Cin,
                                                 float* __restrict__ C,
                                                 int N, int K, int ldc, int ldcin) {
    __shared__ MidSmem s;
    gemm_mid_body<ACT>(s, A, W, bias, Cin, C, N, K, ldc, ldcin,
                       blockIdx.x * 64, blockIdx.y * 64);
}

// se/ho fused: z=0 -> sentemb = sent@seW^T+seb ; z=1 -> hemb = h@hoW^T+hob
__global__ void __launch_bounds__(256) sgemm_seho(const float* __restrict__ sent,
                                                  const float* __restrict__ hh,
                                                  const float* __restrict__ seW,
                                                  const float* __restrict__ hoW,
                                                  const float* __restrict__ seb,
                                                  const float* __restrict__ hob,
                                                  float* __restrict__ se_out,
                                                  float* __restrict__ ho_out) {
    __shared__ MidSmem s;
    if (blockIdx.z == 0)
        gemm_mid_body<0>(s, sent, seW, seb, nullptr, se_out, HH, RR, HH, 0,
                         blockIdx.x * 64, blockIdx.y * 64);
    else
        gemm_mid_body<0>(s, hh, hoW, hob, nullptr, ho_out, HH, RR, HH, 0,
                         blockIdx.x * 64, blockIdx.y * 64);
}

// ---------------- LSTM pointwise ----------------
__global__ void lstm_kernel(const float* __restrict__ gates, float* __restrict__ c,
                            float* __restrict__ h, float* __restrict__ sent) {
    int idx = blockIdx.x * blockDim.x + threadIdx.x;
    if (idx >= BB * RR) return;
    int b = idx / RR, r = idx % RR;
    const float* g = gates + (size_t)b * G5;
    float ig = sigmoidf_(g[r]);
    float fg = sigmoidf_(g[RR + r]);
    float gg = tanhf(g[2 * RR + r]);
    float og = sigmoidf_(g[3 * RR + r]);
    float sg = sigmoidf_(g[4 * RR + r]);
    float cy = tanhf(fg * c[idx] + ig * gg);
    c[idx] = cy;
    sent[idx] = sg * cy;
    h[idx] = og * cy;
}

// ---------------- fused attention: scores + softmax + cHat + (+hy) ----------------
__global__ void __launch_bounds__(256) attn_chat_kernel(const float* __restrict__ sentemb,
                                                        const float* __restrict__ hemb,
                                                        const float* __restrict__ vemb,
                                                        const float* __restrict__ alW,
                                                        const float* __restrict__ alb,
                                                        const float* __restrict__ sent,
                                                        const float* __restrict__ v,
                                                        const float* __restrict__ h,
                                                        float* __restrict__ x2) {
    int b = blockIdx.x;
    int tid = threadIdx.x;
    __shared__ float sAl[HH];
    __shared__ float sH[HH];
    __shared__ float sSc[224];
    __shared__ float red[256];
    for (int j = tid; j < HH; j += 256) {
        sAl[j] = alW[j];
        sH[j] = hemb[(size_t)b * HH + j];
    }
    __syncthreads();
    int warp = tid >> 5, lane = tid & 31;
    float ab = alb[0];
    for (int a = warp; a < A1; a += 8) {
        const float* e = (a == 0) ? (sentemb + (size_t)b * HH)
                                  : (vemb + ((size_t)b * AA + (a - 1)) * HH);
        float s = 0.0f;
        for (int j = lane; j < HH; j += 32) s += sAl[j] * tanh_fast(e[j] + sH[j]);
#pragma unroll
        for (int o = 16; o > 0; o >>= 1) s += __shfl_down_sync(0xffffffffu, s, o);
        if (lane == 0) sSc[a] = s + ab;
    }
    __syncthreads();
    // softmax over sSc[0..196]
    float m = -INFINITY;
    for (int a = tid; a < A1; a += 256) m = fmaxf(m, sSc[a]);
    red[tid] = m; __syncthreads();
    for (int st = 128; st > 0; st >>= 1) {
        if (tid < st) red[tid] = fmaxf(red[tid], red[tid + st]);
        __syncthreads();
    }
    float mx = red[0]; __syncthreads();
    float sum = 0.0f;
    for (int a = tid; a < A1; a += 256) sum += expf(sSc[a] - mx);
    red[tid] = sum; __syncthreads();
    for (int st = 128; st > 0; st >>= 1) {
        if (tid < st) red[tid] += red[tid + st];
        __syncthreads();
    }
    float inv = 1.0f / red[0];
    __syncthreads();
    for (int a = tid; a < A1; a += 256) sSc[a] = expf(sSc[a] - mx) * inv;
    __syncthreads();
    // cHat + hy for r = tid and r = tid + 256
    int r0 = tid, r1 = tid + 256;
    float a0 = sSc[0];
    float acc0 = a0 * sent[(size_t)b * RR + r0];
    float acc1 = a0 * sent[(size_t)b * RR + r1];
    const float* vp = v + (size_t)b * AA * RR;
    for (int a = 0; a < AA; a++) {
        float s = sSc[a + 1];
        acc0 += s * vp[(size_t)a * RR + r0];
        acc1 += s * vp[(size_t)a * RR + r1];
    }
    x2[(size_t)b * RR + r0] = acc0 + h[(size_t)b * RR + r0];
    x2[(size_t)b * RR + r1] = acc1 + h[(size_t)b * RR + r1];
}

// ---------------- log-softmax in place ----------------
__global__ void __launch_bounds__(256) logsm_kernel(float* __restrict__ base) {
    int b = blockIdx.x;
    float* p = base + (size_t)b * OUT_ROW;
    __shared__ float red[256];
    int tid = threadIdx.x;
    float m = -INFINITY;
    for (int i = tid; i < BV; i += 256) m = fmaxf(m, p[i]);
    red[tid] = m; __syncthreads();
    for (int st = 128; st > 0; st >>= 1) {
        if (tid < st) red[tid] = fmaxf(red[tid], red[tid + st]);
        __syncthreads();
    }
    float mx = red[0]; __syncthreads();
    float sum = 0.0f;
    for (int i = tid; i < BV; i += 256) sum += expf(p[i] - mx);
    red[tid] = sum; __syncthreads();
    for (int st = 128; st > 0; st >>= 1) {
        if (tid < st) red[tid] += red[tid + st];
        __syncthreads();
    }
    float lse = mx + logf(red[0]);
    for (int i = tid; i < BV; i += 256) p[i] -= lse;
}

// ---------------- launch ----------------
extern "C" void kernel_launch(void* const* d_in, const int* in_sizes, int n_in,
                              void* d_out, int out_size) {
    const float* att  = (const float*)d_in[0];
    const int*   seq  = (const int*)d_in[1];
    const float* E    = (const float*)d_in[2];
    const float* w_ih = (const float*)d_in[3];
    const float* w_hh = (const float*)d_in[4];
    const float* aeW  = (const float*)d_in[5];
    const float* aeb  = (const float*)d_in[6];
    const float* c2aW = (const float*)d_in[7];
    const float* c2ab = (const float*)d_in[8];
    const float* seW  = (const float*)d_in[9];
    const float* seb  = (const float*)d_in[10];
    const float* hoW  = (const float*)d_in[11];
    const float* hob  = (const float*)d_in[12];
    const float* alW  = (const float*)d_in[13];
    const float* alb  = (const float*)d_in[14];
    const float* a2hW = (const float*)d_in[15];
    const float* a2hb = (const float*)d_in[16];
    const float* lgW  = (const float*)d_in[17];
    const float* lgb  = (const float*)d_in[18];
    float* out = (float*)d_out;

    float *v, *vemb, *xall, *wihp, *gx, *gates, *h, *c, *sent, *sentemb, *hemb, *x2, *hout;
    cudaGetSymbolAddress((void**)&v, g_v);
    cudaGetSymbolAddress((void**)&vemb, g_vemb);
    cudaGetSymbolAddress((void**)&xall, g_xall);
    cudaGetSymbolAddress((void**)&wihp, g_wihp);
    cudaGetSymbolAddress((void**)&gx, g_gx);
    cudaGetSymbolAddress((void**)&gates, g_gates);
    cudaGetSymbolAddress((void**)&h, g_h);
    cudaGetSymbolAddress((void**)&c, g_c);
    cudaGetSymbolAddress((void**)&sent, g_sent);
    cudaGetSymbolAddress((void**)&sentemb, g_sentemb);
    cudaGetSymbolAddress((void**)&hemb, g_hemb);
    cudaGetSymbolAddress((void**)&x2, g_x2);
    cudaGetSymbolAddress((void**)&hout, g_hout);

    // Hoisted work
    init_state_kernel<<<(BB * RR + 255) / 256, 256>>>(h, c);
    pad_wih_kernel<<<(G5 * DP + 255) / 256, 256>>>(w_ih, wihp);
    embed_all_kernel<<<(TT * BB * DP + 255) / 256, 256>>>(seq, E, xall);
    sgemm_big<true><<<dim3(MROWS / 128, RR / 128), 256>>>(att, aeW, aeb, v, MROWS, RR, FEAT);
    sgemm_big<false><<<dim3(MROWS / 128, RR / 128), 256>>>(v, c2aW, c2ab, vemb, MROWS, RR, RR);
    // gx[2560,2560] = xall[2560,304] @ wihp^T
    sgemm_mid<0><<<dim3(TT * BB / 64, G5 / 64), 256>>>(xall, wihp, nullptr, nullptr, gx,
                                                       G5, DP, G5, 0);

    for (int t = 0; t < TT; t++) {
        // gates = gx[t] + h @ w_hh^T
        sgemm_mid<0><<<dim3(BB / 64, G5 / 64), 256>>>(h, w_hh, nullptr,
                                                      gx + (size_t)t * BB * G5, gates,
                                                      G5, RR, G5, G5);
        lstm_kernel<<<(BB * RR + 255) / 256, 256>>>(gates, c, h, sent);
        sgemm_seho<<<dim3(BB / 64, HH / 64, 2), 256>>>(sent, h, seW, hoW, seb, hob,
                                                       sentemb, hemb);
        attn_chat_kernel<<<BB, 256>>>(sentemb, hemb, vemb, alW, alb, sent, v, h, x2);
        sgemm_mid<1><<<dim3(BB / 64, RR / 64), 256>>>(x2, a2hW, a2hb, nullptr, hout,
                                                      RR, RR, RR, 0);
        sgemm_mid<0><<<dim3(BB / 64, (BV + 63) / 64), 256>>>(hout, lgW, lgb, nullptr,
                                                             out + (size_t)t * BV,
                                                             BV, RR, OUT_ROW, 0);
        logsm_kernel<<<BB, 256>>>(out + (size_t)t * BV);
    }
}

// round 5
// speedup vs baseline: 1.8835x; 1.4780x over previous
#include <cuda_runtime.h>
#include <cuda_bf16.h>
#include <math.h>
#include <stddef.h>
#include <stdint.h>

// Problem dims
#define BV 7800
#define BVP 7808        // padded vocab (61*128)
#define DD 300
#define DPK 320         // padded D for bf16 GEMM (10*32)
#define RR 512
#define HH 512
#define FEAT 2048
#define BB 128
#define AA 196
#define TT 20
#define A1 197
#define G5 2560
#define MROWS 25088
#define OUT_ROW 156000

// ---------------- device scratch ----------------
__device__ __nv_bfloat16 g_att_bf[MROWS * FEAT];
__device__ __nv_bfloat16 g_aeW_bf[RR * FEAT];
__device__ __nv_bfloat16 g_c2aW_bf[RR * RR];
__device__ __nv_bfloat16 g_v_bf[MROWS * RR];
__device__ __nv_bfloat16 g_xall_bf[TT * BB * DPK];
__device__ __nv_bfloat16 g_wih_bf[G5 * DPK];
__device__ __nv_bfloat16 g_lgW_bf[BVP * RR];
__device__ __nv_bfloat16 g_hout_bf[BB * RR];
__device__ float g_v[MROWS * RR];
__device__ float g_vemb[MROWS * RR];
__device__ float g_gx[TT * BB * G5];
__device__ float g_gates[BB * G5];
__device__ float g_h[BB * RR];
__device__ float g_c[BB * RR];
__device__ float g_sent[BB * RR];
__device__ float g_sentemb[BB * HH];
__device__ float g_hemb[BB * HH];
__device__ float g_x2[BB * RR];
__device__ float g_hout[BB * RR];

// ---------------- helpers ----------------
__device__ __forceinline__ float sigmoidf_(float x) { return 1.0f / (1.0f + expf(-x)); }
__device__ __forceinline__ float tanh_fast(float x) {
    float y;
    asm("tanh.approx.f32 %0, %1;" : "=f"(y) : "f"(x));
    return y;
}

__device__ __forceinline__ void mma16816(float* c, const uint32_t* a, uint32_t b0, uint32_t b1) {
    asm volatile(
        "mma.sync.aligned.m16n8k16.row.col.f32.bf16.bf16.f32 "
        "{%0,%1,%2,%3}, {%4,%5,%6,%7}, {%8,%9}, {%0,%1,%2,%3};"
        : "+f"(c[0]), "+f"(c[1]), "+f"(c[2]), "+f"(c[3])
        : "r"(a[0]), "r"(a[1]), "r"(a[2]), "r"(a[3]), "r"(b0), "r"(b1));
}

// ---------------- bf16 mma.sync GEMM: C[M,N] = act(A[M,K]@W[N,K]^T + bias) ----------------
// Tile 128x128xK, BK=32, 256 threads = 8 warps (4 m x 2 n), warp tile 32x64.
// Requires M%128==0, Npad%128==0 (grid), K%32==0. Guards output cols to Nlog.
// C fragment rows are g and g+8 (m16n8k16): stores use row0 and row0+8.
#define PADR 40  // smem row stride in bf16 (20 b32)
template <bool RELU, bool HAS_BIAS, bool WBF>
__global__ void __launch_bounds__(256) gemm_mma(
    const __nv_bfloat16* __restrict__ A, const __nv_bfloat16* __restrict__ W,
    const float* __restrict__ bias, float* __restrict__ C,
    __nv_bfloat16* __restrict__ Cbf, int Nlog, int K, size_t ldc, int ldbf) {
    __shared__ alignas(16) __nv_bfloat16 sA[128 * PADR];
    __shared__ alignas(16) __nv_bfloat16 sB[128 * PADR];
    const uint32_t* s32A = (const uint32_t*)sA;
    const uint32_t* s32B = (const uint32_t*)sB;

    int tid = threadIdx.x;
    int wid = tid >> 5, lane = tid & 31;
    int wm = wid >> 1, wn = wid & 1;       // warp grid 4x2
    int g = lane >> 2, tg = lane & 3;
    int bm = blockIdx.x * 128, bn = blockIdx.y * 128;

    // gmem->smem mapping: 512 uint4 per operand, 2 per thread
    int i0 = tid, i1 = tid + 256;
    int r0g = i0 >> 2, s0g = i0 & 3;
    int r1g = i1 >> 2, s1g = i1 & 3;
    const uint4* Ag0 = (const uint4*)(A + (size_t)(bm + r0g) * K + s0g * 8);
    const uint4* Ag1 = (const uint4*)(A + (size_t)(bm + r1g) * K + s1g * 8);
    const uint4* Wg0 = (const uint4*)(W + (size_t)(bn + r0g) * K + s0g * 8);
    const uint4* Wg1 = (const uint4*)(W + (size_t)(bn + r1g) * K + s1g * 8);
    uint4* sA0 = (uint4*)((char*)sA + r0g * (PADR * 2) + s0g * 16);
    uint4* sA1 = (uint4*)((char*)sA + r1g * (PADR * 2) + s1g * 16);
    uint4* sB0 = (uint4*)((char*)sB + r0g * (PADR * 2) + s0g * 16);
    uint4* sB1 = (uint4*)((char*)sB + r1g * (PADR * 2) + s1g * 16);

    float acc[2][8][4];
#pragma unroll
    for (int m = 0; m < 2; m++)
#pragma unroll
        for (int n = 0; n < 8; n++)
#pragma unroll
            for (int q = 0; q < 4; q++) acc[m][n][q] = 0.0f;

    for (int k0 = 0; k0 < K; k0 += 32) {
        uint4 a0 = Ag0[k0 / 8], a1 = Ag1[k0 / 8];
        uint4 b0 = Wg0[k0 / 8], b1 = Wg1[k0 / 8];
        __syncthreads();
        *sA0 = a0; *sA1 = a1; *sB0 = b0; *sB1 = b1;
        __syncthreads();
#pragma unroll
        for (int ks = 0; ks < 2; ks++) {
            int kb2 = ks * 8;
            uint32_t af[2][4];
#pragma unroll
            for (int m = 0; m < 2; m++) {
                int r = (wm * 32 + m * 16 + g) * 20;
                af[m][0] = s32A[r + kb2 + tg];
                af[m][1] = s32A[r + 160 + kb2 + tg];        // +8 rows
                af[m][2] = s32A[r + kb2 + 4 + tg];
                af[m][3] = s32A[r + 160 + kb2 + 4 + tg];
            }
#pragma unroll
            for (int n = 0; n < 8; n++) {
                int rb = (wn * 64 + n * 8 + g) * 20;
                uint32_t bf0 = s32B[rb + kb2 + tg];
                uint32_t bf1 = s32B[rb + kb2 + 4 + tg];
                mma16816(acc[0][n], af[0], bf0, bf1);
                mma16816(acc[1][n], af[1], bf0, bf1);
            }
        }
    }

    // epilogue: c0/c1 -> row0, c2/c3 -> row0+8
#pragma unroll
    for (int m = 0; m < 2; m++) {
        int row0 = bm + wm * 32 + m * 16 + g;
#pragma unroll
        for (int n = 0; n < 8; n++) {
            int col = bn + wn * 64 + n * 8 + tg * 2;
            float v0 = acc[m][n][0], v1 = acc[m][n][1];
            float v2 = acc[m][n][2], v3 = acc[m][n][3];
            if (HAS_BIAS) {
                if (col < Nlog) { float bb = bias[col]; v0 += bb; v2 += bb; }
                if (col + 1 < Nlog) { float bb = bias[col + 1]; v1 += bb; v3 += bb; }
            }
            if (RELU) {
                v0 = fmaxf(v0, 0.f); v1 = fmaxf(v1, 0.f);
                v2 = fmaxf(v2, 0.f); v3 = fmaxf(v3, 0.f);
            }
            if (col + 1 < Nlog) {
                *(float2*)(C + (size_t)row0 * ldc + col) = make_float2(v0, v1);
                *(float2*)(C + (size_t)(row0 + 8) * ldc + col) = make_float2(v2, v3);
            } else if (col < Nlog) {
                C[(size_t)row0 * ldc + col] = v0;
                C[(size_t)(row0 + 8) * ldc + col] = v2;
            }
            if (WBF) {
                *(__nv_bfloat162*)(Cbf + (size_t)row0 * ldbf + col) =
                    __floats2bfloat162_rn(v0, v1);
                *(__nv_bfloat162*)(Cbf + (size_t)(row0 + 8) * ldbf + col) =
                    __floats2bfloat162_rn(v2, v3);
            }
        }
    }
}

// ---------------- conversions ----------------
__global__ void cvt_f2b4(const float* __restrict__ in, __nv_bfloat16* __restrict__ out, int n4) {
    int i = blockIdx.x * blockDim.x + threadIdx.x;
    if (i >= n4) return;
    float4 v = ((const float4*)in)[i];
    __nv_bfloat162* p = (__nv_bfloat162*)out + i * 2;
    p[0] = __floats2bfloat162_rn(v.x, v.y);
    p[1] = __floats2bfloat162_rn(v.z, v.w);
}
__global__ void pad_wih_bf(const float* __restrict__ w, __nv_bfloat16* __restrict__ wp) {
    int idx = blockIdx.x * blockDim.x + threadIdx.x;
    if (idx >= G5 * DPK) return;
    int r = idx / DPK, c = idx % DPK;
    wp[idx] = (c < DD) ? __float2bfloat16(w[r * DD + c]) : __float2bfloat16(0.0f);
}
__global__ void pad_lgw_bf(const float* __restrict__ w, __nv_bfloat16* __restrict__ wp) {
    int idx = blockIdx.x * blockDim.x + threadIdx.x;
    if (idx >= BVP * RR) return;
    int r = idx / RR, c = idx % RR;
    wp[idx] = (r < BV) ? __float2bfloat16(w[(size_t)r * RR + c]) : __float2bfloat16(0.0f);
}
__global__ void embed_all_bf(const int* __restrict__ seq, const float* __restrict__ E,
                             __nv_bfloat16* __restrict__ xall) {
    int idx = blockIdx.x * blockDim.x + threadIdx.x;
    if (idx >= TT * BB * DPK) return;
    int d = idx % DPK;
    int row = idx / DPK;
    int t = row / BB, b = row % BB;
    float v = 0.0f;
    if (d < DD) {
        int tok = seq[b * 21 + t];
        v = fmaxf(E[(size_t)tok * DD + d], 0.0f);
    }
    xall[idx] = __float2bfloat16(v);
}
__global__ void init_state_kernel(float* h, float* c) {
    int i = blockIdx.x * blockDim.x + threadIdx.x;
    if (i < BB * RR) { h[i] = 0.0f; c[i] = 0.0f; }
}

// ---------------- mid fp32 SGEMM (small per-step matmuls) ----------------
struct MidSmem { float As[16][64]; float Bs[16][64]; };

template <int ACT>
__device__ __forceinline__ void gemm_mid_body(MidSmem& s, const float* __restrict__ A,
                                              const float* __restrict__ W,
                                              const float* __restrict__ bias,
                                              const float* __restrict__ Cin,
                                              float* __restrict__ C, int N, int K,
                                              int ldc, int ldcin, int bm, int bn) {
    int tid = threadIdx.x;
    int lr = tid & 63;
    int lk = (tid >> 6) * 4;
    int tx = tid & 15, ty = tid >> 4;
    const float* Aptr = A + (size_t)(bm + lr) * K + lk;
    int wn = bn + lr;
    bool wok = (wn < N);
    const float* Wptr = W + (size_t)(wok ? wn : 0) * K + lk;
    float acc[4][4];
#pragma unroll
    for (int i = 0; i < 4; i++)
#pragma unroll
        for (int j = 0; j < 4; j++) acc[i][j] = 0.0f;
    for (int k0 = 0; k0 < K; k0 += 16) {
        float4 a4 = *(const float4*)(Aptr + k0);
        float4 b4 = wok ? *(const float4*)(Wptr + k0) : make_float4(0.f, 0.f, 0.f, 0.f);
        __syncthreads();
        s.As[lk + 0][lr] = a4.x; s.As[lk + 1][lr] = a4.y;
        s.As[lk + 2][lr] = a4.z; s.As[lk + 3][lr] = a4.w;
        s.Bs[lk + 0][lr] = b4.x; s.Bs[lk + 1][lr] = b4.y;
        s.Bs[lk + 2][lr] = b4.z; s.Bs[lk + 3][lr] = b4.w;
        __syncthreads();
#pragma unroll
        for (int k = 0; k < 16; k++) {
            float ra[4], rb[4];
#pragma unroll
            for (int i = 0; i < 4; i++) ra[i] = s.As[k][ty * 4 + i];
#pragma unroll
            for (int j = 0; j < 4; j++) rb[j] = s.Bs[k][tx * 4 + j];
#pragma unroll
            for (int i = 0; i < 4; i++)
#pragma unroll
                for (int j = 0; j < 4; j++) acc[i][j] += ra[i] * rb[j];
        }
    }
#pragma unroll
    for (int i = 0; i < 4; i++) {
        int m = bm + ty * 4 + i;
#pragma unroll
        for (int j = 0; j < 4; j++) {
            int n = bn + tx * 4 + j;
            if (n < N) {
                float v = acc[i][j];
                if (bias) v += bias[n];
                if (Cin) v += Cin[(size_t)m * ldcin + n];
                if (ACT == 1) v = tanhf(v);
                C[(size_t)m * ldc + n] = v;
            }
        }
    }
}

template <int ACT>
__global__ void __launch_bounds__(256) sgemm_mid(const float* __restrict__ A,
                                                 const float* __restrict__ W,
                                                 const float* __restrict__ bias,
                                                 const float* __restrict__ Cin,
                                                 float* __restrict__ C, int N, int K,
                                                 int ldc, int ldcin) {
    __shared__ MidSmem s;
    gemm_mid_body<ACT>(s, A, W, bias, Cin, C, N, K, ldc, ldcin,
                       blockIdx.x * 64, blockIdx.y * 64);
}

__global__ void __launch_bounds__(256) sgemm_seho(const float* __restrict__ sent,
                                                  const float* __restrict__ hh,
                                                  const float* __restrict__ seW,
                                                  const float* __restrict__ hoW,
                                                  const float* __restrict__ seb,
                                                  const float* __restrict__ hob,
                                                  float* __restrict__ se_out,
                                                  float* __restrict__ ho_out) {
    __shared__ MidSmem s;
    if (blockIdx.z == 0)
        gemm_mid_body<0>(s, sent, seW, seb, nullptr, se_out, HH, RR, HH, 0,
                         blockIdx.x * 64, blockIdx.y * 64);
    else
        gemm_mid_body<0>(s, hh, hoW, hob, nullptr, ho_out, HH, RR, HH, 0,
                         blockIdx.x * 64, blockIdx.y * 64);
}

// ---------------- LSTM pointwise ----------------
__global__ void lstm_kernel(const float* __restrict__ gates, float* __restrict__ c,
                            float* __restrict__ h, float* __restrict__ sent) {
    int idx = blockIdx.x * blockDim.x + threadIdx.x;
    if (idx >= BB * RR) return;
    int b = idx / RR, r = idx % RR;
    const float* g = gates + (size_t)b * G5;
    float ig = sigmoidf_(g[r]);
    float fg = sigmoidf_(g[RR + r]);
    float gg = tanhf(g[2 * RR + r]);
    float og = sigmoidf_(g[3 * RR + r]);
    float sg = sigmoidf_(g[4 * RR + r]);
    float cy = tanhf(fg * c[idx] + ig * gg);
    c[idx] = cy;
    sent[idx] = sg * cy;
    h[idx] = og * cy;
}

// ---------------- fused attention ----------------
__global__ void __launch_bounds__(256) attn_chat_kernel(const float* __restrict__ sentemb,
                                                        const float* __restrict__ hemb,
                                                        const float* __restrict__ vemb,
                                                        const float* __restrict__ alW,
                                                        const float* __restrict__ alb,
                                                        const float* __restrict__ sent,
                                                        const float* __restrict__ v,
                                                        const float* __restrict__ h,
                                                        float* __restrict__ x2) {
    int b = blockIdx.x;
    int tid = threadIdx.x;
    __shared__ float sAl[HH];
    __shared__ float sH[HH];
    __shared__ float sSc[224];
    __shared__ float red[256];
    for (int j = tid; j < HH; j += 256) {
        sAl[j] = alW[j];
        sH[j] = hemb[(size_t)b * HH + j];
    }
    __syncthreads();
    int warp = tid >> 5, lane = tid & 31;
    float ab = alb[0];
    for (int a = warp; a < A1; a += 8) {
        const float* e = (a == 0) ? (sentemb + (size_t)b * HH)
                                  : (vemb + ((size_t)b * AA + (a - 1)) * HH);
        float s = 0.0f;
        for (int j = lane; j < HH; j += 32) s += sAl[j] * tanh_fast(e[j] + sH[j]);
#pragma unroll
        for (int o = 16; o > 0; o >>= 1) s += __shfl_down_sync(0xffffffffu, s, o);
        if (lane == 0) sSc[a] = s + ab;
    }
    __syncthreads();
    float m = -INFINITY;
    for (int a = tid; a < A1; a += 256) m = fmaxf(m, sSc[a]);
    red[tid] = m; __syncthreads();
    for (int st = 128; st > 0; st >>= 1) {
        if (tid < st) red[tid] = fmaxf(red[tid], red[tid + st]);
        __syncthreads();
    }
    float mx = red[0]; __syncthreads();
    float sum = 0.0f;
    for (int a = tid; a < A1; a += 256) sum += expf(sSc[a] - mx);
    red[tid] = sum; __syncthreads();
    for (int st = 128; st > 0; st >>= 1) {
        if (tid < st) red[tid] += red[tid + st];
        __syncthreads();
    }
    float inv = 1.0f / red[0];
    __syncthreads();
    for (int a = tid; a < A1; a += 256) sSc[a] = expf(sSc[a] - mx) * inv;
    __syncthreads();
    int r0 = tid, r1 = tid + 256;
    float a0 = sSc[0];
    float acc0 = a0 * sent[(size_t)b * RR + r0];
    float acc1 = a0 * sent[(size_t)b * RR + r1];
    const float* vp = v + (size_t)b * AA * RR;
    for (int a = 0; a < AA; a++) {
        float s = sSc[a + 1];
        acc0 += s * vp[(size_t)a * RR + r0];
        acc1 += s * vp[(size_t)a * RR + r1];
    }
    x2[(size_t)b * RR + r0] = acc0 + h[(size_t)b * RR + r0];
    x2[(size_t)b * RR + r1] = acc1 + h[(size_t)b * RR + r1];
}

// ---------------- log-softmax in place ----------------
__global__ void __launch_bounds__(256) logsm_kernel(float* __restrict__ base) {
    int b = blockIdx.x;
    float* p = base + (size_t)b * OUT_ROW;
    __shared__ float red[256];
    int tid = threadIdx.x;
    float m = -INFINITY;
    for (int i = tid; i < BV; i += 256) m = fmaxf(m, p[i]);
    red[tid] = m; __syncthreads();
    for (int st = 128; st > 0; st >>= 1) {
        if (tid < st) red[tid] = fmaxf(red[tid], red[tid + st]);
        __syncthreads();
    }
    float mx = red[0]; __syncthreads();
    float sum = 0.0f;
    for (int i = tid; i < BV; i += 256) sum += expf(p[i] - mx);
    red[tid] = sum; __syncthreads();
    for (int st = 128; st > 0; st >>= 1) {
        if (tid < st) red[tid] += red[tid + st];
        __syncthreads();
    }
    float lse = mx + logf(red[0]);
    for (int i = tid; i < BV; i += 256) p[i] -= lse;
}

// ---------------- launch ----------------
extern "C" void kernel_launch(void* const* d_in, const int* in_sizes, int n_in,
                              void* d_out, int out_size) {
    const float* att  = (const float*)d_in[0];
    const int*   seq  = (const int*)d_in[1];
    const float* E    = (const float*)d_in[2];
    const float* w_ih = (const float*)d_in[3];
    const float* w_hh = (const float*)d_in[4];
    const float* aeW  = (const float*)d_in[5];
    const float* aeb  = (const float*)d_in[6];
    const float* c2aW = (const float*)d_in[7];
    const float* c2ab = (const float*)d_in[8];
    const float* seW  = (const float*)d_in[9];
    const float* seb  = (const float*)d_in[10];
    const float* hoW  = (const float*)d_in[11];
    const float* hob  = (const float*)d_in[12];
    const float* alW  = (const float*)d_in[13];
    const float* alb  = (const float*)d_in[14];
    const float* a2hW = (const float*)d_in[15];
    const float* a2hb = (const float*)d_in[16];
    const float* lgW  = (const float*)d_in[17];
    const float* lgb  = (const float*)d_in[18];
    float* out = (float*)d_out;

    __nv_bfloat16 *att_bf, *aeW_bf, *c2aW_bf, *v_bf, *xall_bf, *wih_bf, *lgW_bf, *hout_bf;
    float *v, *vemb, *gx, *gates, *h, *c, *sent, *sentemb, *hemb, *x2, *hout;
    cudaGetSymbolAddress((void**)&att_bf, g_att_bf);
    cudaGetSymbolAddress((void**)&aeW_bf, g_aeW_bf);
    cudaGetSymbolAddress((void**)&c2aW_bf, g_c2aW_bf);
    cudaGetSymbolAddress((void**)&v_bf, g_v_bf);
    cudaGetSymbolAddress((void**)&xall_bf, g_xall_bf);
    cudaGetSymbolAddress((void**)&wih_bf, g_wih_bf);
    cudaGetSymbolAddress((void**)&lgW_bf, g_lgW_bf);
    cudaGetSymbolAddress((void**)&hout_bf, g_hout_bf);
    cudaGetSymbolAddress((void**)&v, g_v);
    cudaGetSymbolAddress((void**)&vemb, g_vemb);
    cudaGetSymbolAddress((void**)&gx, g_gx);
    cudaGetSymbolAddress((void**)&gates, g_gates);
    cudaGetSymbolAddress((void**)&h, g_h);
    cudaGetSymbolAddress((void**)&c, g_c);
    cudaGetSymbolAddress((void**)&sent, g_sent);
    cudaGetSymbolAddress((void**)&sentemb, g_sentemb);
    cudaGetSymbolAddress((void**)&hemb, g_hemb);
    cudaGetSymbolAddress((void**)&x2, g_x2);
    cudaGetSymbolAddress((void**)&hout, g_hout);

    // Conversions + hoisted
    init_state_kernel<<<(BB * RR + 255) / 256, 256>>>(h, c);
    cvt_f2b4<<<(MROWS * FEAT / 4 + 255) / 256, 256>>>(att, att_bf, MROWS * FEAT / 4);
    cvt_f2b4<<<(RR * FEAT / 4 + 255) / 256, 256>>>(aeW, aeW_bf, RR * FEAT / 4);
    cvt_f2b4<<<(RR * RR / 4 + 255) / 256, 256>>>(c2aW, c2aW_bf, RR * RR / 4);
    pad_wih_bf<<<(G5 * DPK + 255) / 256, 256>>>(w_ih, wih_bf);
    pad_lgw_bf<<<(BVP * RR + 255) / 256, 256>>>(lgW, lgW_bf);
    embed_all_bf<<<(TT * BB * DPK + 255) / 256, 256>>>(seq, E, xall_bf);

    // v = relu(att@aeW^T + aeb) (fp32 + bf16 copies)
    gemm_mma<true, true, true><<<dim3(MROWS / 128, RR / 128), 256>>>(
        att_bf, aeW_bf, aeb, v, v_bf, RR, FEAT, RR, RR);
    // vemb = v@c2aW^T + c2ab
    gemm_mma<false, true, false><<<dim3(MROWS / 128, RR / 128), 256>>>(
        v_bf, c2aW_bf, c2ab, vemb, nullptr, RR, RR, RR, 0);
    // gx = xall@w_ih^T
    gemm_mma<false, false, false><<<dim3(TT * BB / 128, G5 / 128), 256>>>(
        xall_bf, wih_bf, nullptr, gx, nullptr, G5, DPK, G5, 0);

    for (int t = 0; t < TT; t++) {
        sgemm_mid<0><<<dim3(BB / 64, G5 / 64), 256>>>(h, w_hh, nullptr,
                                                      gx + (size_t)t * BB * G5, gates,
                                                      G5, RR, G5, G5);
        lstm_kernel<<<(BB * RR + 255) / 256, 256>>>(gates, c, h, sent);
        sgemm_seho<<<dim3(BB / 64, HH / 64, 2), 256>>>(sent, h, seW, hoW, seb, hob,
                                                       sentemb, hemb);
        attn_chat_kernel<<<BB, 256>>>(sentemb, hemb, vemb, alW, alb, sent, v, h, x2);
        sgemm_mid<1><<<dim3(BB / 64, RR / 64), 256>>>(x2, a2hW, a2hb, nullptr, hout,
                                                      RR, RR, RR, 0);
        cvt_f2b4<<<(BB * RR / 4 + 255) / 256, 256>>>(hout, hout_bf, BB * RR / 4);
        gemm_mma<false, true, false><<<dim3(1, BVP / 128), 256>>>(
            hout_bf, lgW_bf, lgb, out + (size_t)t * BV, nullptr, BV, RR, OUT_ROW, 0);
        logsm_kernel<<<BB, 256>>>(out + (size_t)t * BV);
    }
}

// round 6
// speedup vs baseline: 3.8031x; 2.0192x over previous
#include <cuda_runtime.h>
#include <cuda_bf16.h>
#include <math.h>
#include <stddef.h>
#include <stdint.h>

// Problem dims
#define BV 7800
#define BVP 7808        // padded vocab (61*128)
#define DD 300
#define DPK 320         // padded D for bf16 GEMM (10*32)
#define RR 512
#define HH 512
#define FEAT 2048
#define BB 128
#define AA 196
#define TT 20
#define A1 197
#define G5 2560
#define MROWS 25088
#define OUT_ROW 156000

// ---------------- device scratch ----------------
__device__ __nv_bfloat16 g_att_bf[MROWS * FEAT];
__device__ __nv_bfloat16 g_aeW_bf[RR * FEAT];
__device__ __nv_bfloat16 g_c2aW_bf[RR * RR];
__device__ __nv_bfloat16 g_whh_bf[G5 * RR];
__device__ __nv_bfloat16 g_seW_bf[HH * RR];
__device__ __nv_bfloat16 g_hoW_bf[HH * RR];
__device__ __nv_bfloat16 g_a2hW_bf[RR * RR];
__device__ __nv_bfloat16 g_v_bf[MROWS * RR];
__device__ __nv_bfloat16 g_vemb_bf[MROWS * RR];
__device__ __nv_bfloat16 g_xall_bf[TT * BB * DPK];
__device__ __nv_bfloat16 g_wih_bf[G5 * DPK];
__device__ __nv_bfloat16 g_lgW_bf[BVP * RR];
__device__ __nv_bfloat16 g_hout_bf[BB * RR];
__device__ __nv_bfloat16 g_h_bf[BB * RR];
__device__ __nv_bfloat16 g_sent_bf[BB * RR];
__device__ __nv_bfloat16 g_x2_bf[BB * RR];
__device__ float g_gx[TT * BB * G5];
__device__ float g_gates[BB * G5];
__device__ float g_h[BB * RR];
__device__ float g_c[BB * RR];
__device__ float g_sentemb[BB * HH];
__device__ float g_hemb[BB * HH];

// ---------------- helpers ----------------
__device__ __forceinline__ float sigmoidf_(float x) { return 1.0f / (1.0f + expf(-x)); }
__device__ __forceinline__ float tanh_fast(float x) {
    float y;
    asm("tanh.approx.f32 %0, %1;" : "=f"(y) : "f"(x));
    return y;
}
__device__ __forceinline__ void mma16816(float* c, const uint32_t* a, uint32_t b0, uint32_t b1) {
    asm volatile(
        "mma.sync.aligned.m16n8k16.row.col.f32.bf16.bf16.f32 "
        "{%0,%1,%2,%3}, {%4,%5,%6,%7}, {%8,%9}, {%0,%1,%2,%3};"
        : "+f"(c[0]), "+f"(c[1]), "+f"(c[2]), "+f"(c[3])
        : "r"(a[0]), "r"(a[1]), "r"(a[2]), "r"(a[3]), "r"(b0), "r"(b1));
}
__device__ __forceinline__ void cpa16(uint32_t dst, const void* src) {
    asm volatile("cp.async.cg.shared.global [%0], [%1], 16;" :: "r"(dst), "l"(src));
}
#define CP_COMMIT() asm volatile("cp.async.commit_group;" ::: "memory")
#define CP_WAIT1()  asm volatile("cp.async.wait_group 1;" ::: "memory")
#define CP_WAIT0()  asm volatile("cp.async.wait_group 0;" ::: "memory")

// ---------------- bf16 mma.sync GEMM core ----------------
// C[M,N] = act(A[M,K]@W[N,K]^T [+ bias] [+ Cin]); tile 128x128, BK=32,
// 256 thr = 8 warps (4m x 2n), warp tile 32x64, 2-stage cp.async pipeline.
// Requires M%128==0 (bm), Npad%128==0 (bn), K%32==0; col guard to Nlog.
#define PADR 40                 // smem row stride in bf16
#define BUFW (128 * PADR)       // bf16 elems per stage
struct MmaSmem { __nv_bfloat16 sA[2][BUFW]; __nv_bfloat16 sB[2][BUFW]; };

// ACT: 0 none, 1 relu, 2 tanh
template <int ACT, bool HAS_BIAS, bool WF32, bool WBF, bool HAS_CIN>
__device__ __forceinline__ void mma_body(
    MmaSmem& sm,
    const __nv_bfloat16* __restrict__ A, const __nv_bfloat16* __restrict__ W,
    const float* __restrict__ bias, const float* __restrict__ Cin,
    float* __restrict__ C, __nv_bfloat16* __restrict__ Cbf,
    int Nlog, int K, size_t ldc, int ldcin, int ldbf, int bm, int bn) {

    int tid = threadIdx.x;
    int wid = tid >> 5, lane = tid & 31;
    int wm = wid >> 1, wn = wid & 1;
    int g = lane >> 2, tg = lane & 3;

    int i0 = tid, i1 = tid + 256;
    int r0g = i0 >> 2, s0g = i0 & 3;
    int r1g = i1 >> 2, s1g = i1 & 3;
    const char* Ag0 = (const char*)(A + (size_t)(bm + r0g) * K + s0g * 8);
    const char* Ag1 = (const char*)(A + (size_t)(bm + r1g) * K + s1g * 8);
    const char* Wg0 = (const char*)(W + (size_t)(bn + r0g) * K + s0g * 8);
    const char* Wg1 = (const char*)(W + (size_t)(bn + r1g) * K + s1g * 8);
    uint32_t dA0 = (uint32_t)__cvta_generic_to_shared(&sm.sA[0][0]) + r0g * (PADR * 2) + s0g * 16;
    uint32_t dA1 = (uint32_t)__cvta_generic_to_shared(&sm.sA[0][0]) + r1g * (PADR * 2) + s1g * 16;
    uint32_t dB0 = (uint32_t)__cvta_generic_to_shared(&sm.sB[0][0]) + r0g * (PADR * 2) + s0g * 16;
    uint32_t dB1 = (uint32_t)__cvta_generic_to_shared(&sm.sB[0][0]) + r1g * (PADR * 2) + s1g * 16;

    float acc[2][8][4];
#pragma unroll
    for (int m = 0; m < 2; m++)
#pragma unroll
        for (int n = 0; n < 8; n++)
#pragma unroll
            for (int q = 0; q < 4; q++) acc[m][n][q] = 0.0f;

    // prefetch stage 0
    {
        cpa16(dA0, Ag0); cpa16(dA1, Ag1);
        cpa16(dB0, Wg0); cpa16(dB1, Wg1);
        CP_COMMIT();
    }

    for (int k0 = 0; k0 < K; k0 += 32) {
        int cur = (k0 >> 5) & 1;
        if (k0 + 32 < K) {
            uint32_t off = (cur ^ 1) * (BUFW * 2);
            size_t kb = (size_t)(k0 + 32) * 2;
            cpa16(dA0 + off, Ag0 + kb); cpa16(dA1 + off, Ag1 + kb);
            cpa16(dB0 + off, Wg0 + kb); cpa16(dB1 + off, Wg1 + kb);
            CP_COMMIT();
            CP_WAIT1();
        } else {
            CP_WAIT0();
        }
        __syncthreads();
        const uint32_t* s32A = (const uint32_t*)sm.sA[cur];
        const uint32_t* s32B = (const uint32_t*)sm.sB[cur];
#pragma unroll
        for (int ks = 0; ks < 2; ks++) {
            int kb2 = ks * 8;
            uint32_t af[2][4];
#pragma unroll
            for (int m = 0; m < 2; m++) {
                int r = (wm * 32 + m * 16 + g) * 20;
                af[m][0] = s32A[r + kb2 + tg];
                af[m][1] = s32A[r + 160 + kb2 + tg];
                af[m][2] = s32A[r + kb2 + 4 + tg];
                af[m][3] = s32A[r + 160 + kb2 + 4 + tg];
            }
#pragma unroll
            for (int n = 0; n < 8; n++) {
                int rb = (wn * 64 + n * 8 + g) * 20;
                uint32_t bf0 = s32B[rb + kb2 + tg];
                uint32_t bf1 = s32B[rb + kb2 + 4 + tg];
                mma16816(acc[0][n], af[0], bf0, bf1);
                mma16816(acc[1][n], af[1], bf0, bf1);
            }
        }
        __syncthreads();
    }

    // epilogue: c0/c1 -> row0, c2/c3 -> row0+8
#pragma unroll
    for (int m = 0; m < 2; m++) {
        int row0 = bm + wm * 32 + m * 16 + g;
#pragma unroll
        for (int n = 0; n < 8; n++) {
            int col = bn + wn * 64 + n * 8 + tg * 2;
            float v0 = acc[m][n][0], v1 = acc[m][n][1];
            float v2 = acc[m][n][2], v3 = acc[m][n][3];
            if (HAS_BIAS) {
                if (col < Nlog) { float bb = bias[col]; v0 += bb; v2 += bb; }
                if (col + 1 < Nlog) { float bb = bias[col + 1]; v1 += bb; v3 += bb; }
            }
            if (HAS_CIN) {
                if (col + 1 < Nlog) {
                    float2 c0 = *(const float2*)(Cin + (size_t)row0 * ldcin + col);
                    float2 c1 = *(const float2*)(Cin + (size_t)(row0 + 8) * ldcin + col);
                    v0 += c0.x; v1 += c0.y; v2 += c1.x; v3 += c1.y;
                } else if (col < Nlog) {
                    v0 += Cin[(size_t)row0 * ldcin + col];
                    v2 += Cin[(size_t)(row0 + 8) * ldcin + col];
                }
            }
            if (ACT == 1) {
                v0 = fmaxf(v0, 0.f); v1 = fmaxf(v1, 0.f);
                v2 = fmaxf(v2, 0.f); v3 = fmaxf(v3, 0.f);
            } else if (ACT == 2) {
                v0 = tanhf(v0); v1 = tanhf(v1); v2 = tanhf(v2); v3 = tanhf(v3);
            }
            if (WF32) {
                if (col + 1 < Nlog) {
                    *(float2*)(C + (size_t)row0 * ldc + col) = make_float2(v0, v1);
                    *(float2*)(C + (size_t)(row0 + 8) * ldc + col) = make_float2(v2, v3);
                } else if (col < Nlog) {
                    C[(size_t)row0 * ldc + col] = v0;
                    C[(size_t)(row0 + 8) * ldc + col] = v2;
                }
            }
            if (WBF) {
                *(__nv_bfloat162*)(Cbf + (size_t)row0 * ldbf + col) =
                    __floats2bfloat162_rn(v0, v1);
                *(__nv_bfloat162*)(Cbf + (size_t)(row0 + 8) * ldbf + col) =
                    __floats2bfloat162_rn(v2, v3);
            }
        }
    }
}

template <int ACT, bool HAS_BIAS, bool WF32, bool WBF, bool HAS_CIN>
__global__ void __launch_bounds__(256) gemm_mma(
    const __nv_bfloat16* __restrict__ A, const __nv_bfloat16* __restrict__ W,
    const float* __restrict__ bias, const float* __restrict__ Cin,
    float* __restrict__ C, __nv_bfloat16* __restrict__ Cbf,
    int Nlog, int K, size_t ldc, int ldcin, int ldbf) {
    __shared__ MmaSmem sm;
    mma_body<ACT, HAS_BIAS, WF32, WBF, HAS_CIN>(sm, A, W, bias, Cin, C, Cbf, Nlog, K,
                                                ldc, ldcin, ldbf,
                                                blockIdx.x * 128, blockIdx.y * 128);
}

// se/ho fused (z=0: sentemb, z=1: hemb)
__global__ void __launch_bounds__(256) gemm_seho(
    const __nv_bfloat16* __restrict__ sent_bf, const __nv_bfloat16* __restrict__ h_bf,
    const __nv_bfloat16* __restrict__ seW, const __nv_bfloat16* __restrict__ hoW,
    const float* __restrict__ seb, const float* __restrict__ hob,
    float* __restrict__ sentemb, float* __restrict__ hemb) {
    __shared__ MmaSmem sm;
    if (blockIdx.z == 0)
        mma_body<0, true, true, false, false>(sm, sent_bf, seW, seb, nullptr, sentemb,
                                              nullptr, HH, RR, HH, 0, 0, 0,
                                              blockIdx.y * 128);
    else
        mma_body<0, true, true, false, false>(sm, h_bf, hoW, hob, nullptr, hemb,
                                              nullptr, HH, RR, HH, 0, 0, 0,
                                              blockIdx.y * 128);
}

// ---------------- conversions ----------------
__global__ void cvt_f2b4(const float* __restrict__ in, __nv_bfloat16* __restrict__ out, int n4) {
    int i = blockIdx.x * blockDim.x + threadIdx.x;
    if (i >= n4) return;
    float4 v = ((const float4*)in)[i];
    __nv_bfloat162* p = (__nv_bfloat162*)out + i * 2;
    p[0] = __floats2bfloat162_rn(v.x, v.y);
    p[1] = __floats2bfloat162_rn(v.z, v.w);
}
__global__ void pad_wih_bf(const float* __restrict__ w, __nv_bfloat16* __restrict__ wp) {
    int idx = blockIdx.x * blockDim.x + threadIdx.x;
    if (idx >= G5 * DPK) return;
    int r = idx / DPK, c = idx % DPK;
    wp[idx] = (c < DD) ? __float2bfloat16(w[r * DD + c]) : __float2bfloat16(0.0f);
}
__global__ void pad_lgw_bf(const float* __restrict__ w, __nv_bfloat16* __restrict__ wp) {
    int idx = blockIdx.x * blockDim.x + threadIdx.x;
    if (idx >= BVP * RR) return;
    int r = idx / RR, c = idx % RR;
    wp[idx] = (r < BV) ? __float2bfloat16(w[(size_t)r * RR + c]) : __float2bfloat16(0.0f);
}
__global__ void embed_all_bf(const int* __restrict__ seq, const float* __restrict__ E,
                             __nv_bfloat16* __restrict__ xall) {
    int idx = blockIdx.x * blockDim.x + threadIdx.x;
    if (idx >= TT * BB * DPK) return;
    int d = idx % DPK;
    int row = idx / DPK;
    int t = row / BB, b = row % BB;
    float v = 0.0f;
    if (d < DD) {
        int tok = seq[b * 21 + t];
        v = fmaxf(E[(size_t)tok * DD + d], 0.0f);
    }
    xall[idx] = __float2bfloat16(v);
}
__global__ void init_state_kernel(float* h, float* c, __nv_bfloat16* h_bf) {
    int i = blockIdx.x * blockDim.x + threadIdx.x;
    if (i < BB * RR) { h[i] = 0.0f; c[i] = 0.0f; h_bf[i] = __float2bfloat16(0.0f); }
}

// ---------------- LSTM pointwise ----------------
__global__ void lstm_kernel(const float* __restrict__ gates, float* __restrict__ c,
                            float* __restrict__ h, __nv_bfloat16* __restrict__ h_bf,
                            __nv_bfloat16* __restrict__ sent_bf) {
    int idx = blockIdx.x * blockDim.x + threadIdx.x;
    if (idx >= BB * RR) return;
    int b = idx / RR, r = idx % RR;
    const float* g = gates + (size_t)b * G5;
    float ig = sigmoidf_(g[r]);
    float fg = sigmoidf_(g[RR + r]);
    float gg = tanhf(g[2 * RR + r]);
    float og = sigmoidf_(g[3 * RR + r]);
    float sg = sigmoidf_(g[4 * RR + r]);
    float cy = tanhf(fg * c[idx] + ig * gg);
    c[idx] = cy;
    float hy = og * cy;
    h[idx] = hy;
    h_bf[idx] = __float2bfloat16(hy);
    sent_bf[idx] = __float2bfloat16(sg * cy);
}

// ---------------- fused attention (bf16 data) ----------------
__global__ void __launch_bounds__(256) attn_chat_kernel(
    const float* __restrict__ sentemb, const float* __restrict__ hemb,
    const __nv_bfloat16* __restrict__ vemb, const float* __restrict__ alW,
    const float* __restrict__ alb, const __nv_bfloat16* __restrict__ sent_bf,
    const __nv_bfloat16* __restrict__ v_bf, const float* __restrict__ h,
    __nv_bfloat16* __restrict__ x2_bf) {
    int b = blockIdx.x;
    int tid = threadIdx.x;
    __shared__ float sAl[HH];
    __shared__ float sH[HH];
    __shared__ float sSc[224];
    __shared__ float red[256];
    for (int j = tid; j < HH; j += 256) {
        sAl[j] = alW[j];
        sH[j] = hemb[(size_t)b * HH + j];
    }
    __syncthreads();
    int warp = tid >> 5, lane = tid & 31;
    float ab = alb[0];
    for (int a = warp; a < A1; a += 8) {
        float s = 0.0f;
        if (a == 0) {
            const float* e = sentemb + (size_t)b * HH;
            for (int j = lane; j < HH; j += 32) s += sAl[j] * tanh_fast(e[j] + sH[j]);
        } else {
            const __nv_bfloat16* e = vemb + ((size_t)b * AA + (a - 1)) * HH;
            for (int j = lane; j < HH; j += 32)
                s += sAl[j] * tanh_fast(__bfloat162float(e[j]) + sH[j]);
        }
#pragma unroll
        for (int o = 16; o > 0; o >>= 1) s += __shfl_down_sync(0xffffffffu, s, o);
        if (lane == 0) sSc[a] = s + ab;
    }
    __syncthreads();
    float m = -INFINITY;
    for (int a = tid; a < A1; a += 256) m = fmaxf(m, sSc[a]);
    red[tid] = m; __syncthreads();
    for (int st = 128; st > 0; st >>= 1) {
        if (tid < st) red[tid] = fmaxf(red[tid], red[tid + st]);
        __syncthreads();
    }
    float mx = red[0]; __syncthreads();
    float sum = 0.0f;
    for (int a = tid; a < A1; a += 256) sum += expf(sSc[a] - mx);
    red[tid] = sum; __syncthreads();
    for (int st = 128; st > 0; st >>= 1) {
        if (tid < st) red[tid] += red[tid + st];
        __syncthreads();
    }
    float inv = 1.0f / red[0];
    __syncthreads();
    for (int a = tid; a < A1; a += 256) sSc[a] = expf(sSc[a] - mx) * inv;
    __syncthreads();
    // cHat + hy for r pair (2*tid, 2*tid+1)
    const __nv_bfloat162* vp2 = (const __nv_bfloat162*)(v_bf + (size_t)b * AA * RR);
    __nv_bfloat162 sv = ((const __nv_bfloat162*)(sent_bf + (size_t)b * RR))[tid];
    float a0 = sSc[0];
    float acc0 = a0 * __low2float(sv);
    float acc1 = a0 * __high2float(sv);
    for (int a = 0; a < AA; a++) {
        __nv_bfloat162 vv = vp2[(size_t)a * (RR / 2) + tid];
        float s = sSc[a + 1];
        acc0 += s * __low2float(vv);
        acc1 += s * __high2float(vv);
    }
    float2 hv = *(const float2*)(h + (size_t)b * RR + 2 * tid);
    ((__nv_bfloat162*)(x2_bf + (size_t)b * RR))[tid] =
        __floats2bfloat162_rn(acc0 + hv.x, acc1 + hv.y);
}

// ---------------- log-softmax in place ----------------
__global__ void __launch_bounds__(256) logsm_kernel(float* __restrict__ base) {
    int b = blockIdx.x;
    float* p = base + (size_t)b * OUT_ROW;
    __shared__ float red[256];
    int tid = threadIdx.x;
    float m = -INFINITY;
    for (int i = tid; i < BV; i += 256) m = fmaxf(m, p[i]);
    red[tid] = m; __syncthreads();
    for (int st = 128; st > 0; st >>= 1) {
        if (tid < st) red[tid] = fmaxf(red[tid], red[tid + st]);
        __syncthreads();
    }
    float mx = red[0]; __syncthreads();
    float sum = 0.0f;
    for (int i = tid; i < BV; i += 256) sum += expf(p[i] - mx);
    red[tid] = sum; __syncthreads();
    for (int st = 128; st > 0; st >>= 1) {
        if (tid < st) red[tid] += red[tid + st];
        __syncthreads();
    }
    float lse = mx + logf(red[0]);
    for (int i = tid; i < BV; i += 256) p[i] -= lse;
}

// ---------------- launch ----------------
extern "C" void kernel_launch(void* const* d_in, const int* in_sizes, int n_in,
                              void* d_out, int out_size) {
    const float* att  = (const float*)d_in[0];
    const int*   seq  = (const int*)d_in[1];
    const float* E    = (const float*)d_in[2];
    const float* w_ih = (const float*)d_in[3];
    const float* w_hh = (const float*)d_in[4];
    const float* aeW  = (const float*)d_in[5];
    const float* aeb  = (const float*)d_in[6];
    const float* c2aW = (const float*)d_in[7];
    const float* c2ab = (const float*)d_in[8];
    const float* seW  = (const float*)d_in[9];
    const float* seb  = (const float*)d_in[10];
    const float* hoW  = (const float*)d_in[11];
    const float* hob  = (const float*)d_in[12];
    const float* alW  = (const float*)d_in[13];
    const float* alb  = (const float*)d_in[14];
    const float* a2hW = (const float*)d_in[15];
    const float* a2hb = (const float*)d_in[16];
    const float* lgW  = (const float*)d_in[17];
    const float* lgb  = (const float*)d_in[18];
    float* out = (float*)d_out;

    __nv_bfloat16 *att_bf, *aeW_bf, *c2aW_bf, *whh_bf, *seW_bf, *hoW_bf, *a2hW_bf;
    __nv_bfloat16 *v_bf, *vemb_bf, *xall_bf, *wih_bf, *lgW_bf, *hout_bf, *h_bf, *sent_bf, *x2_bf;
    float *gx, *gates, *h, *c, *sentemb, *hemb;
    cudaGetSymbolAddress((void**)&att_bf, g_att_bf);
    cudaGetSymbolAddress((void**)&aeW_bf, g_aeW_bf);
    cudaGetSymbolAddress((void**)&c2aW_bf, g_c2aW_bf);
    cudaGetSymbolAddress((void**)&whh_bf, g_whh_bf);
    cudaGetSymbolAddress((void**)&seW_bf, g_seW_bf);
    cudaGetSymbolAddress((void**)&hoW_bf, g_hoW_bf);
    cudaGetSymbolAddress((void**)&a2hW_bf, g_a2hW_bf);
    cudaGetSymbolAddress((void**)&v_bf, g_v_bf);
    cudaGetSymbolAddress((void**)&vemb_bf, g_vemb_bf);
    cudaGetSymbolAddress((void**)&xall_bf, g_xall_bf);
    cudaGetSymbolAddress((void**)&wih_bf, g_wih_bf);
    cudaGetSymbolAddress((void**)&lgW_bf, g_lgW_bf);
    cudaGetSymbolAddress((void**)&hout_bf, g_hout_bf);
    cudaGetSymbolAddress((void**)&h_bf, g_h_bf);
    cudaGetSymbolAddress((void**)&sent_bf, g_sent_bf);
    cudaGetSymbolAddress((void**)&x2_bf, g_x2_bf);
    cudaGetSymbolAddress((void**)&gx, g_gx);
    cudaGetSymbolAddress((void**)&gates, g_gates);
    cudaGetSymbolAddress((void**)&h, g_h);
    cudaGetSymbolAddress((void**)&c, g_c);
    cudaGetSymbolAddress((void**)&sentemb, g_sentemb);
    cudaGetSymbolAddress((void**)&hemb, g_hemb);

    // Conversions + hoisted
    init_state_kernel<<<(BB * RR + 255) / 256, 256>>>(h, c, h_bf);
    cvt_f2b4<<<(MROWS * FEAT / 4 + 255) / 256, 256>>>(att, att_bf, MROWS * FEAT / 4);
    cvt_f2b4<<<(RR * FEAT / 4 + 255) / 256, 256>>>(aeW, aeW_bf, RR * FEAT / 4);
    cvt_f2b4<<<(RR * RR / 4 + 255) / 256, 256>>>(c2aW, c2aW_bf, RR * RR / 4);
    cvt_f2b4<<<(G5 * RR / 4 + 255) / 256, 256>>>(w_hh, whh_bf, G5 * RR / 4);
    cvt_f2b4<<<(HH * RR / 4 + 255) / 256, 256>>>(seW, seW_bf, HH * RR / 4);
    cvt_f2b4<<<(HH * RR / 4 + 255) / 256, 256>>>(hoW, hoW_bf, HH * RR / 4);
    cvt_f2b4<<<(RR * RR / 4 + 255) / 256, 256>>>(a2hW, a2hW_bf, RR * RR / 4);
    pad_wih_bf<<<(G5 * DPK + 255) / 256, 256>>>(w_ih, wih_bf);
    pad_lgw_bf<<<(BVP * RR + 255) / 256, 256>>>(lgW, lgW_bf);
    embed_all_bf<<<(TT * BB * DPK + 255) / 256, 256>>>(seq, E, xall_bf);

    // v_bf = relu(att@aeW^T + aeb)   (bf16 only)
    gemm_mma<1, true, false, true, false><<<dim3(MROWS / 128, RR / 128), 256>>>(
        att_bf, aeW_bf, aeb, nullptr, nullptr, v_bf, RR, FEAT, 0, 0, RR);
    // vemb_bf = v@c2aW^T + c2ab     (bf16 only)
    gemm_mma<0, true, false, true, false><<<dim3(MROWS / 128, RR / 128), 256>>>(
        v_bf, c2aW_bf, c2ab, nullptr, nullptr, vemb_bf, RR, RR, 0, 0, RR);
    // gx = xall@w_ih^T (fp32)
    gemm_mma<0, false, true, false, false><<<dim3(TT * BB / 128, G5 / 128), 256>>>(
        xall_bf, wih_bf, nullptr, nullptr, gx, nullptr, G5, DPK, G5, 0, 0);

    for (int t = 0; t < TT; t++) {
        // gates = gx[t] + h@w_hh^T
        gemm_mma<0, false, true, false, true><<<dim3(1, G5 / 128), 256>>>(
            h_bf, whh_bf, nullptr, gx + (size_t)t * BB * G5, gates, nullptr,
            G5, RR, G5, G5, 0);
        lstm_kernel<<<(BB * RR + 255) / 256, 256>>>(gates, c, h, h_bf, sent_bf);
        gemm_seho<<<dim3(1, HH / 128, 2), 256>>>(sent_bf, h_bf, seW_bf, hoW_bf,
                                                 seb, hob, sentemb, hemb);
        attn_chat_kernel<<<BB, 256>>>(sentemb, hemb, vemb_bf, alW, alb, sent_bf,
                                      v_bf, h, x2_bf);
        // hout_bf = tanh(x2@a2hW^T + a2hb)   (bf16 only)
        gemm_mma<2, true, false, true, false><<<dim3(1, RR / 128), 256>>>(
            x2_bf, a2hW_bf, a2hb, nullptr, nullptr, hout_bf, RR, RR, 0, 0, RR);
        // logits
        gemm_mma<0, true, true, false, false><<<dim3(1, BVP / 128), 256>>>(
            hout_bf, lgW_bf, lgb, nullptr, out + (size_t)t * BV, nullptr,
            BV, RR, OUT_ROW, 0, 0);
        logsm_kernel<<<BB, 256>>>(out + (size_t)t * BV);
    }
}

// round 7
// speedup vs baseline: 4.3440x; 1.1422x over previous
#include <cuda_runtime.h>
#include <cuda_bf16.h>
#include <math.h>
#include <stddef.h>
#include <stdint.h>

// Problem dims
#define BV 7800
#define BVP 7808        // padded vocab (61*128)
#define DD 300
#define DPK 320         // padded D for bf16 GEMM (10*32)
#define RR 512
#define HH 512
#define FEAT 2048
#define BB 128
#define AA 196
#define TT 20
#define A1 197
#define G5 2560
#define MROWS 25088
#define OUT_ROW 156000

// ---------------- device scratch ----------------
__device__ __nv_bfloat16 g_att_bf[MROWS * FEAT];
__device__ __nv_bfloat16 g_aeW_bf[RR * FEAT];
__device__ __nv_bfloat16 g_c2aW_bf[RR * RR];
__device__ __nv_bfloat16 g_whh_bf[G5 * RR];
__device__ __nv_bfloat16 g_seW_bf[HH * RR];
__device__ __nv_bfloat16 g_hoW_bf[HH * RR];
__device__ __nv_bfloat16 g_a2hW_bf[RR * RR];
__device__ __nv_bfloat16 g_v_bf[MROWS * RR];
__device__ __nv_bfloat16 g_vemb_bf[MROWS * RR];
__device__ __nv_bfloat16 g_xall_bf[TT * BB * DPK];
__device__ __nv_bfloat16 g_wih_bf[G5 * DPK];
__device__ __nv_bfloat16 g_lgW_bf[BVP * RR];
__device__ __nv_bfloat16 g_hout_bf[2][BB * RR];   // double buffered (cross-stream)
__device__ __nv_bfloat16 g_h_bf[BB * RR];
__device__ __nv_bfloat16 g_sent_bf[BB * RR];
__device__ __nv_bfloat16 g_x2_bf[BB * RR];
__device__ float g_gx[TT * BB * G5];
__device__ float g_gates[BB * G5];
__device__ float g_h[BB * RR];
__device__ float g_c[BB * RR];
__device__ float g_sentemb[BB * HH];
__device__ float g_hemb[BB * HH];

// ---------------- static stream/event resources (host objects, no device mem) ----
static cudaStream_t s_b = nullptr;
static cudaEvent_t s_evFork = nullptr, s_evGx = nullptr;
static cudaEvent_t s_evA[TT], s_evB[TT];
static struct StreamInit {
    StreamInit() {
        cudaStreamCreateWithFlags(&s_b, cudaStreamNonBlocking);
        cudaEventCreateWithFlags(&s_evFork, cudaEventDisableTiming);
        cudaEventCreateWithFlags(&s_evGx, cudaEventDisableTiming);
        for (int t = 0; t < TT; t++) {
            cudaEventCreateWithFlags(&s_evA[t], cudaEventDisableTiming);
            cudaEventCreateWithFlags(&s_evB[t], cudaEventDisableTiming);
        }
    }
} s_streamInit;

// ---------------- helpers ----------------
__device__ __forceinline__ float sigmoidf_(float x) { return 1.0f / (1.0f + expf(-x)); }
__device__ __forceinline__ float tanh_fast(float x) {
    float y;
    asm("tanh.approx.f32 %0, %1;" : "=f"(y) : "f"(x));
    return y;
}
__device__ __forceinline__ void mma16816(float* c, const uint32_t* a, uint32_t b0, uint32_t b1) {
    asm volatile(
        "mma.sync.aligned.m16n8k16.row.col.f32.bf16.bf16.f32 "
        "{%0,%1,%2,%3}, {%4,%5,%6,%7}, {%8,%9}, {%0,%1,%2,%3};"
        : "+f"(c[0]), "+f"(c[1]), "+f"(c[2]), "+f"(c[3])
        : "r"(a[0]), "r"(a[1]), "r"(a[2]), "r"(a[3]), "r"(b0), "r"(b1));
}
__device__ __forceinline__ void cpa16(uint32_t dst, const void* src) {
    asm volatile("cp.async.cg.shared.global [%0], [%1], 16;" :: "r"(dst), "l"(src));
}
#define CP_COMMIT() asm volatile("cp.async.commit_group;" ::: "memory")
#define CP_WAIT1()  asm volatile("cp.async.wait_group 1;" ::: "memory")
#define CP_WAIT0()  asm volatile("cp.async.wait_group 0;" ::: "memory")

// ---------------- bf16 mma.sync GEMM core ----------------
#define PADR 40
#define BUFW (128 * PADR)
struct MmaSmem { __nv_bfloat16 sA[2][BUFW]; __nv_bfloat16 sB[2][BUFW]; };

// ACT: 0 none, 1 relu, 2 tanh
template <int ACT, bool HAS_BIAS, bool WF32, bool WBF, bool HAS_CIN>
__device__ __forceinline__ void mma_body(
    MmaSmem& sm,
    const __nv_bfloat16* __restrict__ A, const __nv_bfloat16* __restrict__ W,
    const float* __restrict__ bias, const float* __restrict__ Cin,
    float* __restrict__ C, __nv_bfloat16* __restrict__ Cbf,
    int Nlog, int K, size_t ldc, int ldcin, int ldbf, int bm, int bn) {

    int tid = threadIdx.x;
    int wid = tid >> 5, lane = tid & 31;
    int wm = wid >> 1, wn = wid & 1;
    int g = lane >> 2, tg = lane & 3;

    int i0 = tid, i1 = tid + 256;
    int r0g = i0 >> 2, s0g = i0 & 3;
    int r1g = i1 >> 2, s1g = i1 & 3;
    const char* Ag0 = (const char*)(A + (size_t)(bm + r0g) * K + s0g * 8);
    const char* Ag1 = (const char*)(A + (size_t)(bm + r1g) * K + s1g * 8);
    const char* Wg0 = (const char*)(W + (size_t)(bn + r0g) * K + s0g * 8);
    const char* Wg1 = (const char*)(W + (size_t)(bn + r1g) * K + s1g * 8);
    uint32_t dA0 = (uint32_t)__cvta_generic_to_shared(&sm.sA[0][0]) + r0g * (PADR * 2) + s0g * 16;
    uint32_t dA1 = (uint32_t)__cvta_generic_to_shared(&sm.sA[0][0]) + r1g * (PADR * 2) + s1g * 16;
    uint32_t dB0 = (uint32_t)__cvta_generic_to_shared(&sm.sB[0][0]) + r0g * (PADR * 2) + s0g * 16;
    uint32_t dB1 = (uint32_t)__cvta_generic_to_shared(&sm.sB[0][0]) + r1g * (PADR * 2) + s1g * 16;

    float acc[2][8][4];
#pragma unroll
    for (int m = 0; m < 2; m++)
#pragma unroll
        for (int n = 0; n < 8; n++)
#pragma unroll
            for (int q = 0; q < 4; q++) acc[m][n][q] = 0.0f;

    {
        cpa16(dA0, Ag0); cpa16(dA1, Ag1);
        cpa16(dB0, Wg0); cpa16(dB1, Wg1);
        CP_COMMIT();
    }

    for (int k0 = 0; k0 < K; k0 += 32) {
        int cur = (k0 >> 5) & 1;
        if (k0 + 32 < K) {
            uint32_t off = (cur ^ 1) * (BUFW * 2);
            size_t kb = (size_t)(k0 + 32) * 2;
            cpa16(dA0 + off, Ag0 + kb); cpa16(dA1 + off, Ag1 + kb);
            cpa16(dB0 + off, Wg0 + kb); cpa16(dB1 + off, Wg1 + kb);
            CP_COMMIT();
            CP_WAIT1();
        } else {
            CP_WAIT0();
        }
        __syncthreads();
        const uint32_t* s32A = (const uint32_t*)sm.sA[cur];
        const uint32_t* s32B = (const uint32_t*)sm.sB[cur];
#pragma unroll
        for (int ks = 0; ks < 2; ks++) {
            int kb2 = ks * 8;
            uint32_t af[2][4];
#pragma unroll
            for (int m = 0; m < 2; m++) {
                int r = (wm * 32 + m * 16 + g) * 20;
                af[m][0] = s32A[r + kb2 + tg];
                af[m][1] = s32A[r + 160 + kb2 + tg];
                af[m][2] = s32A[r + kb2 + 4 + tg];
                af[m][3] = s32A[r + 160 + kb2 + 4 + tg];
            }
#pragma unroll
            for (int n = 0; n < 8; n++) {
                int rb = (wn * 64 + n * 8 + g) * 20;
                uint32_t bf0 = s32B[rb + kb2 + tg];
                uint32_t bf1 = s32B[rb + kb2 + 4 + tg];
                mma16816(acc[0][n], af[0], bf0, bf1);
                mma16816(acc[1][n], af[1], bf0, bf1);
            }
        }
        __syncthreads();
    }

#pragma unroll
    for (int m = 0; m < 2; m++) {
        int row0 = bm + wm * 32 + m * 16 + g;
#pragma unroll
        for (int n = 0; n < 8; n++) {
            int col = bn + wn * 64 + n * 8 + tg * 2;
            float v0 = acc[m][n][0], v1 = acc[m][n][1];
            float v2 = acc[m][n][2], v3 = acc[m][n][3];
            if (HAS_BIAS) {
                if (col < Nlog) { float bb = bias[col]; v0 += bb; v2 += bb; }
                if (col + 1 < Nlog) { float bb = bias[col + 1]; v1 += bb; v3 += bb; }
            }
            if (HAS_CIN) {
                if (col + 1 < Nlog) {
                    float2 c0 = *(const float2*)(Cin + (size_t)row0 * ldcin + col);
                    float2 c1 = *(const float2*)(Cin + (size_t)(row0 + 8) * ldcin + col);
                    v0 += c0.x; v1 += c0.y; v2 += c1.x; v3 += c1.y;
                } else if (col < Nlog) {
                    v0 += Cin[(size_t)row0 * ldcin + col];
                    v2 += Cin[(size_t)(row0 + 8) * ldcin + col];
                }
            }
            if (ACT == 1) {
                v0 = fmaxf(v0, 0.f); v1 = fmaxf(v1, 0.f);
                v2 = fmaxf(v2, 0.f); v3 = fmaxf(v3, 0.f);
            } else if (ACT == 2) {
                v0 = tanhf(v0); v1 = tanhf(v1); v2 = tanhf(v2); v3 = tanhf(v3);
            }
            if (WF32) {
                if (col + 1 < Nlog) {
                    *(float2*)(C + (size_t)row0 * ldc + col) = make_float2(v0, v1);
                    *(float2*)(C + (size_t)(row0 + 8) * ldc + col) = make_float2(v2, v3);
                } else if (col < Nlog) {
                    C[(size_t)row0 * ldc + col] = v0;
                    C[(size_t)(row0 + 8) * ldc + col] = v2;
                }
            }
            if (WBF) {
                *(__nv_bfloat162*)(Cbf + (size_t)row0 * ldbf + col) =
                    __floats2bfloat162_rn(v0, v1);
                *(__nv_bfloat162*)(Cbf + (size_t)(row0 + 8) * ldbf + col) =
                    __floats2bfloat162_rn(v2, v3);
            }
        }
    }
}

template <int ACT, bool HAS_BIAS, bool WF32, bool WBF, bool HAS_CIN>
__global__ void __launch_bounds__(256) gemm_mma(
    const __nv_bfloat16* __restrict__ A, const __nv_bfloat16* __restrict__ W,
    const float* __restrict__ bias, const float* __restrict__ Cin,
    float* __restrict__ C, __nv_bfloat16* __restrict__ Cbf,
    int Nlog, int K, size_t ldc, int ldcin, int ldbf) {
    __shared__ MmaSmem sm;
    mma_body<ACT, HAS_BIAS, WF32, WBF, HAS_CIN>(sm, A, W, bias, Cin, C, Cbf, Nlog, K,
                                                ldc, ldcin, ldbf,
                                                blockIdx.x * 128, blockIdx.y * 128);
}

// se/ho fused (z=0: sentemb, z=1: hemb)
__global__ void __launch_bounds__(256) gemm_seho(
    const __nv_bfloat16* __restrict__ sent_bf, const __nv_bfloat16* __restrict__ h_bf,
    const __nv_bfloat16* __restrict__ seW, const __nv_bfloat16* __restrict__ hoW,
    const float* __restrict__ seb, const float* __restrict__ hob,
    float* __restrict__ sentemb, float* __restrict__ hemb) {
    __shared__ MmaSmem sm;
    if (blockIdx.z == 0)
        mma_body<0, true, true, false, false>(sm, sent_bf, seW, seb, nullptr, sentemb,
                                              nullptr, HH, RR, HH, 0, 0, 0,
                                              blockIdx.y * 128);
    else
        mma_body<0, true, true, false, false>(sm, h_bf, hoW, hob, nullptr, hemb,
                                              nullptr, HH, RR, HH, 0, 0, 0,
                                              blockIdx.y * 128);
}

// ---------------- conversions ----------------
__global__ void cvt_f2b4(const float* __restrict__ in, __nv_bfloat16* __restrict__ out, int n4) {
    int i = blockIdx.x * blockDim.x + threadIdx.x;
    if (i >= n4) return;
    float4 v = ((const float4*)in)[i];
    __nv_bfloat162* p = (__nv_bfloat162*)out + i * 2;
    p[0] = __floats2bfloat162_rn(v.x, v.y);
    p[1] = __floats2bfloat162_rn(v.z, v.w);
}
__global__ void pad_wih_bf(const float* __restrict__ w, __nv_bfloat16* __restrict__ wp) {
    int idx = blockIdx.x * blockDim.x + threadIdx.x;
    if (idx >= G5 * DPK) return;
    int r = idx / DPK, c = idx % DPK;
    wp[idx] = (c < DD) ? __float2bfloat16(w[r * DD + c]) : __float2bfloat16(0.0f);
}
__global__ void pad_lgw_bf(const float* __restrict__ w, __nv_bfloat16* __restrict__ wp) {
    int idx = blockIdx.x * blockDim.x + threadIdx.x;
    if (idx >= BVP * RR) return;
    int r = idx / RR, c = idx % RR;
    wp[idx] = (r < BV) ? __float2bfloat16(w[(size_t)r * RR + c]) : __float2bfloat16(0.0f);
}
__global__ void embed_all_bf(const int* __restrict__ seq, const float* __restrict__ E,
                             __nv_bfloat16* __restrict__ xall) {
    int idx = blockIdx.x * blockDim.x + threadIdx.x;
    if (idx >= TT * BB * DPK) return;
    int d = idx % DPK;
    int row = idx / DPK;
    int t = row / BB, b = row % BB;
    float v = 0.0f;
    if (d < DD) {
        int tok = seq[b * 21 + t];
        v = fmaxf(E[(size_t)tok * DD + d], 0.0f);
    }
    xall[idx] = __float2bfloat16(v);
}
__global__ void init_state_kernel(float* h, float* c, __nv_bfloat16* h_bf) {
    int i = blockIdx.x * blockDim.x + threadIdx.x;
    if (i < BB * RR) { h[i] = 0.0f; c[i] = 0.0f; h_bf[i] = __float2bfloat16(0.0f); }
}

// ---------------- LSTM pointwise ----------------
__global__ void lstm_kernel(const float* __restrict__ gates, float* __restrict__ c,
                            float* __restrict__ h, __nv_bfloat16* __restrict__ h_bf,
                            __nv_bfloat16* __restrict__ sent_bf) {
    int idx = blockIdx.x * blockDim.x + threadIdx.x;
    if (idx >= BB * RR) return;
    int b = idx / RR, r = idx % RR;
    const float* g = gates + (size_t)b * G5;
    float ig = sigmoidf_(g[r]);
    float fg = sigmoidf_(g[RR + r]);
    float gg = tanhf(g[2 * RR + r]);
    float og = sigmoidf_(g[3 * RR + r]);
    float sg = sigmoidf_(g[4 * RR + r]);
    float cy = tanhf(fg * c[idx] + ig * gg);
    c[idx] = cy;
    float hy = og * cy;
    h[idx] = hy;
    h_bf[idx] = __float2bfloat16(hy);
    sent_bf[idx] = __float2bfloat16(sg * cy);
}

// ---------------- fused attention (bf16 data) ----------------
__global__ void __launch_bounds__(256) attn_chat_kernel(
    const float* __restrict__ sentemb, const float* __restrict__ hemb,
    const __nv_bfloat16* __restrict__ vemb, const float* __restrict__ alW,
    const float* __restrict__ alb, const __nv_bfloat16* __restrict__ sent_bf,
    const __nv_bfloat16* __restrict__ v_bf, const float* __restrict__ h,
    __nv_bfloat16* __restrict__ x2_bf) {
    int b = blockIdx.x;
    int tid = threadIdx.x;
    __shared__ float sAl[HH];
    __shared__ float sH[HH];
    __shared__ float sSc[224];
    __shared__ float red[256];
    for (int j = tid; j < HH; j += 256) {
        sAl[j] = alW[j];
        sH[j] = hemb[(size_t)b * HH + j];
    }
    __syncthreads();
    int warp = tid >> 5, lane = tid & 31;
    float ab = alb[0];
    for (int a = warp; a < A1; a += 8) {
        float s = 0.0f;
        if (a == 0) {
            const float* e = sentemb + (size_t)b * HH;
            for (int j = lane; j < HH; j += 32) s += sAl[j] * tanh_fast(e[j] + sH[j]);
        } else {
            const __nv_bfloat16* e = vemb + ((size_t)b * AA + (a - 1)) * HH;
            for (int j = lane; j < HH; j += 32)
                s += sAl[j] * tanh_fast(__bfloat162float(e[j]) + sH[j]);
        }
#pragma unroll
        for (int o = 16; o > 0; o >>= 1) s += __shfl_down_sync(0xffffffffu, s, o);
        if (lane == 0) sSc[a] = s + ab;
    }
    __syncthreads();
    float m = -INFINITY;
    for (int a = tid; a < A1; a += 256) m = fmaxf(m, sSc[a]);
    red[tid] = m; __syncthreads();
    for (int st = 128; st > 0; st >>= 1) {
        if (tid < st) red[tid] = fmaxf(red[tid], red[tid + st]);
        __syncthreads();
    }
    float mx = red[0]; __syncthreads();
    float sum = 0.0f;
    for (int a = tid; a < A1; a += 256) sum += expf(sSc[a] - mx);
    red[tid] = sum; __syncthreads();
    for (int st = 128; st > 0; st >>= 1) {
        if (tid < st) red[tid] += red[tid + st];
        __syncthreads();
    }
    float inv = 1.0f / red[0];
    __syncthreads();
    for (int a = tid; a < A1; a += 256) sSc[a] = expf(sSc[a] - mx) * inv;
    __syncthreads();
    const __nv_bfloat162* vp2 = (const __nv_bfloat162*)(v_bf + (size_t)b * AA * RR);
    __nv_bfloat162 sv = ((const __nv_bfloat162*)(sent_bf + (size_t)b * RR))[tid];
    float a0 = sSc[0];
    float acc0 = a0 * __low2float(sv);
    float acc1 = a0 * __high2float(sv);
    for (int a = 0; a < AA; a++) {
        __nv_bfloat162 vv = vp2[(size_t)a * (RR / 2) + tid];
        float s = sSc[a + 1];
        acc0 += s * __low2float(vv);
        acc1 += s * __high2float(vv);
    }
    float2 hv = *(const float2*)(h + (size_t)b * RR + 2 * tid);
    ((__nv_bfloat162*)(x2_bf + (size_t)b * RR))[tid] =
        __floats2bfloat162_rn(acc0 + hv.x, acc1 + hv.y);
}

// ---------------- log-softmax in place ----------------
__global__ void __launch_bounds__(256) logsm_kernel(float* __restrict__ base) {
    int b = blockIdx.x;
    float* p = base + (size_t)b * OUT_ROW;
    __shared__ float red[256];
    int tid = threadIdx.x;
    float m = -INFINITY;
    for (int i = tid; i < BV; i += 256) m = fmaxf(m, p[i]);
    red[tid] = m; __syncthreads();
    for (int st = 128; st > 0; st >>= 1) {
        if (tid < st) red[tid] = fmaxf(red[tid], red[tid + st]);
        __syncthreads();
    }
    float mx = red[0]; __syncthreads();
    float sum = 0.0f;
    for (int i = tid; i < BV; i += 256) sum += expf(p[i] - mx);
    red[tid] = sum; __syncthreads();
    for (int st = 128; st > 0; st >>= 1) {
        if (tid < st) red[tid] += red[tid + st];
        __syncthreads();
    }
    float lse = mx + logf(red[0]);
    for (int i = tid; i < BV; i += 256) p[i] -= lse;
}

// ---------------- launch ----------------
extern "C" void kernel_launch(void* const* d_in, const int* in_sizes, int n_in,
                              void* d_out, int out_size) {
    const float* att  = (const float*)d_in[0];
    const int*   seq  = (const int*)d_in[1];
    const float* E    = (const float*)d_in[2];
    const float* w_ih = (const float*)d_in[3];
    const float* w_hh = (const float*)d_in[4];
    const float* aeW  = (const float*)d_in[5];
    const float* aeb  = (const float*)d_in[6];
    const float* c2aW = (const float*)d_in[7];
    const float* c2ab = (const float*)d_in[8];
    const float* seW  = (const float*)d_in[9];
    const float* seb  = (const float*)d_in[10];
    const float* hoW  = (const float*)d_in[11];
    const float* hob  = (const float*)d_in[12];
    const float* alW  = (const float*)d_in[13];
    const float* alb  = (const float*)d_in[14];
    const float* a2hW = (const float*)d_in[15];
    const float* a2hb = (const float*)d_in[16];
    const float* lgW  = (const float*)d_in[17];
    const float* lgb  = (const float*)d_in[18];
    float* out = (float*)d_out;

    __nv_bfloat16 *att_bf, *aeW_bf, *c2aW_bf, *whh_bf, *seW_bf, *hoW_bf, *a2hW_bf;
    __nv_bfloat16 *v_bf, *vemb_bf, *xall_bf, *wih_bf, *lgW_bf, *hout_bf, *h_bf, *sent_bf, *x2_bf;
    float *gx, *gates, *h, *c, *sentemb, *hemb;
    cudaGetSymbolAddress((void**)&att_bf, g_att_bf);
    cudaGetSymbolAddress((void**)&aeW_bf, g_aeW_bf);
    cudaGetSymbolAddress((void**)&c2aW_bf, g_c2aW_bf);
    cudaGetSymbolAddress((void**)&whh_bf, g_whh_bf);
    cudaGetSymbolAddress((void**)&seW_bf, g_seW_bf);
    cudaGetSymbolAddress((void**)&hoW_bf, g_hoW_bf);
    cudaGetSymbolAddress((void**)&a2hW_bf, g_a2hW_bf);
    cudaGetSymbolAddress((void**)&v_bf, g_v_bf);
    cudaGetSymbolAddress((void**)&vemb_bf, g_vemb_bf);
    cudaGetSymbolAddress((void**)&xall_bf, g_xall_bf);
    cudaGetSymbolAddress((void**)&wih_bf, g_wih_bf);
    cudaGetSymbolAddress((void**)&lgW_bf, g_lgW_bf);
    cudaGetSymbolAddress((void**)&hout_bf, g_hout_bf);
    cudaGetSymbolAddress((void**)&h_bf, g_h_bf);
    cudaGetSymbolAddress((void**)&sent_bf, g_sent_bf);
    cudaGetSymbolAddress((void**)&x2_bf, g_x2_bf);
    cudaGetSymbolAddress((void**)&gx, g_gx);
    cudaGetSymbolAddress((void**)&gates, g_gates);
    cudaGetSymbolAddress((void**)&h, g_h);
    cudaGetSymbolAddress((void**)&c, g_c);
    cudaGetSymbolAddress((void**)&sentemb, g_sentemb);
    cudaGetSymbolAddress((void**)&hemb, g_hemb);

    // ---- fork stream B off the (captured) default stream ----
    cudaEventRecord(s_evFork, 0);
    cudaStreamWaitEvent(s_b, s_evFork, 0);

    // Stream B: token path + logits weight prep + gx GEMM (independent of A's chain)
    pad_wih_bf<<<(G5 * DPK + 255) / 256, 256, 0, s_b>>>(w_ih, wih_bf);
    embed_all_bf<<<(TT * BB * DPK + 255) / 256, 256, 0, s_b>>>(seq, E, xall_bf);
    pad_lgw_bf<<<(BVP * RR + 255) / 256, 256, 0, s_b>>>(lgW, lgW_bf);
    gemm_mma<0, false, true, false, false><<<dim3(TT * BB / 128, G5 / 128), 256, 0, s_b>>>(
        xall_bf, wih_bf, nullptr, nullptr, gx, nullptr, G5, DPK, G5, 0, 0);
    cudaEventRecord(s_evGx, s_b);

    // Stream A (default): image path
    init_state_kernel<<<(BB * RR + 255) / 256, 256>>>(h, c, h_bf);
    cvt_f2b4<<<(MROWS * FEAT / 4 + 255) / 256, 256>>>(att, att_bf, MROWS * FEAT / 4);
    cvt_f2b4<<<(RR * FEAT / 4 + 255) / 256, 256>>>(aeW, aeW_bf, RR * FEAT / 4);
    cvt_f2b4<<<(RR * RR / 4 + 255) / 256, 256>>>(c2aW, c2aW_bf, RR * RR / 4);
    cvt_f2b4<<<(G5 * RR / 4 + 255) / 256, 256>>>(w_hh, whh_bf, G5 * RR / 4);
    cvt_f2b4<<<(HH * RR / 4 + 255) / 256, 256>>>(seW, seW_bf, HH * RR / 4);
    cvt_f2b4<<<(HH * RR / 4 + 255) / 256, 256>>>(hoW, hoW_bf, HH * RR / 4);
    cvt_f2b4<<<(RR * RR / 4 + 255) / 256, 256>>>(a2hW, a2hW_bf, RR * RR / 4);
    gemm_mma<1, true, false, true, false><<<dim3(MROWS / 128, RR / 128), 256>>>(
        att_bf, aeW_bf, aeb, nullptr, nullptr, v_bf, RR, FEAT, 0, 0, RR);
    gemm_mma<0, true, false, true, false><<<dim3(MROWS / 128, RR / 128), 256>>>(
        v_bf, c2aW_bf, c2ab, nullptr, nullptr, vemb_bf, RR, RR, 0, 0, RR);

    // A waits for gx before the recurrent loop
    cudaStreamWaitEvent(0, s_evGx, 0);

    for (int t = 0; t < TT; t++) {
        __nv_bfloat16* hb = hout_bf + (size_t)(t & 1) * (BB * RR);
        // gates = gx[t] + h@w_hh^T
        gemm_mma<0, false, true, false, true><<<dim3(1, G5 / 128), 256>>>(
            h_bf, whh_bf, nullptr, gx + (size_t)t * BB * G5, gates, nullptr,
            G5, RR, G5, G5, 0);
        lstm_kernel<<<(BB * RR + 255) / 256, 256>>>(gates, c, h, h_bf, sent_bf);
        gemm_seho<<<dim3(1, HH / 128, 2), 256>>>(sent_bf, h_bf, seW_bf, hoW_bf,
                                                 seb, hob, sentemb, hemb);
        attn_chat_kernel<<<BB, 256>>>(sentemb, hemb, vemb_bf, alW, alb, sent_bf,
                                      v_bf, h, x2_bf);
        // a2h(t) writes hout_bf[t&1]; must wait until B finished logits(t-2) on it
        if (t >= 2) cudaStreamWaitEvent(0, s_evB[t - 2], 0);
        gemm_mma<2, true, false, true, false><<<dim3(1, RR / 128), 256>>>(
            x2_bf, a2hW_bf, a2hb, nullptr, nullptr, hb, RR, RR, 0, 0, RR);
        cudaEventRecord(s_evA[t], 0);

        // Stream B: logits + log-softmax for step t (overlaps with A's step t+1)
        cudaStreamWaitEvent(s_b, s_evA[t], 0);
        gemm_mma<0, true, true, false, false><<<dim3(1, BVP / 128), 256, 0, s_b>>>(
            hb, lgW_bf, lgb, nullptr, out + (size_t)t * BV, nullptr,
            BV, RR, OUT_ROW, 0, 0);
        logsm_kernel<<<BB, 256, 0, s_b>>>(out + (size_t)t * BV);
        cudaEventRecord(s_evB[t], s_b);
    }

    // join B back into the captured origin stream
    cudaStreamWaitEvent(0, s_evB[TT - 1], 0);
}

// round 8
// speedup vs baseline: 4.9638x; 1.1427x over previous
#include <cuda_runtime.h>
#include <cuda_bf16.h>
#include <math.h>
#include <stddef.h>
#include <stdint.h>

// Problem dims
#define BV 7800
#define BVP 7808
#define DD 300
#define DPK 320
#define RR 512
#define HH 512
#define FEAT 2048
#define BB 128
#define AA 196
#define TT 20
#define A1 197
#define G5 2560
#define MROWS 25088
#define OUT_ROW 156000
#define GRIDP 128        // persistent grid size

// ---------------- device scratch ----------------
__device__ __nv_bfloat16 g_att_bf[MROWS * FEAT];
__device__ __nv_bfloat16 g_aeW_bf[RR * FEAT];
__device__ __nv_bfloat16 g_c2aW_bf[RR * RR];
__device__ __nv_bfloat16 g_whh_bf[G5 * RR];
__device__ __nv_bfloat16 g_seW_bf[HH * RR];
__device__ __nv_bfloat16 g_hoW_bf[HH * RR];
__device__ __nv_bfloat16 g_a2hW_bf[RR * RR];
__device__ __nv_bfloat16 g_v_bf[MROWS * RR];
__device__ __nv_bfloat16 g_vemb_bf[MROWS * RR];
__device__ __nv_bfloat16 g_xall_bf[TT * BB * DPK];
__device__ __nv_bfloat16 g_wih_bf[G5 * DPK];
__device__ __nv_bfloat16 g_lgW_bf[BVP * RR];
__device__ __nv_bfloat16 g_hout_all[TT * BB * RR];
__device__ __nv_bfloat16 g_h_bf[BB * RR];
__device__ __nv_bfloat16 g_sent_bf[BB * RR];
__device__ __nv_bfloat16 g_x2_bf[BB * RR];
__device__ float g_gx[TT * BB * G5];
__device__ float g_gates[BB * G5];
__device__ float g_h[BB * RR];
__device__ float g_c[BB * RR];
__device__ float g_sentemb[BB * HH];
__device__ float g_hemb[BB * HH];
// software grid barrier state
__device__ unsigned g_bar_count = 0;
__device__ volatile unsigned g_bar_sense = 0;

// ---------------- static stream/event resources ----------------
static cudaStream_t s_b = nullptr;
static cudaEvent_t s_evFork = nullptr, s_evGx = nullptr;
static struct StreamInit {
    StreamInit() {
        cudaStreamCreateWithFlags(&s_b, cudaStreamNonBlocking);
        cudaEventCreateWithFlags(&s_evFork, cudaEventDisableTiming);
        cudaEventCreateWithFlags(&s_evGx, cudaEventDisableTiming);
    }
} s_streamInit;

// ---------------- helpers ----------------
__device__ __forceinline__ float sigmoidf_(float x) { return 1.0f / (1.0f + expf(-x)); }
__device__ __forceinline__ float tanh_fast(float x) {
    float y;
    asm("tanh.approx.f32 %0, %1;" : "=f"(y) : "f"(x));
    return y;
}
__device__ __forceinline__ void mma16816(float* c, const uint32_t* a, uint32_t b0, uint32_t b1) {
    asm volatile(
        "mma.sync.aligned.m16n8k16.row.col.f32.bf16.bf16.f32 "
        "{%0,%1,%2,%3}, {%4,%5,%6,%7}, {%8,%9}, {%0,%1,%2,%3};"
        : "+f"(c[0]), "+f"(c[1]), "+f"(c[2]), "+f"(c[3])
        : "r"(a[0]), "r"(a[1]), "r"(a[2]), "r"(a[3]), "r"(b0), "r"(b1));
}
__device__ __forceinline__ void cpa16(uint32_t dst, const void* src) {
    asm volatile("cp.async.cg.shared.global [%0], [%1], 16;" :: "r"(dst), "l"(src));
}
#define CP_COMMIT() asm volatile("cp.async.commit_group;" ::: "memory")
#define CP_WAIT1()  asm volatile("cp.async.wait_group 1;" ::: "memory")
#define CP_WAIT0()  asm volatile("cp.async.wait_group 0;" ::: "memory")

// grid barrier (all GRIDP CTAs resident; sense-reversing)
__device__ __forceinline__ void gbar(unsigned sense) {
    __syncthreads();
    if (threadIdx.x == 0) {
        __threadfence();
        unsigned arrived = atomicAdd(&g_bar_count, 1u);
        if (arrived == GRIDP - 1) {
            g_bar_count = 0;
            __threadfence();
            g_bar_sense = sense;
        } else {
            while (g_bar_sense != sense) __nanosleep(64);
        }
        __threadfence();
    }
    __syncthreads();
}

// ---------------- bf16 mma.sync GEMM core ----------------
#define PADR 40
#define BUFW (128 * PADR)
struct MmaSmem { __nv_bfloat16 sA[2][BUFW]; __nv_bfloat16 sB[2][BUFW]; };
struct AttnSmem { float sAl[HH]; float sH[HH]; float sSc[224]; float red[256]; };
union StepSmem { MmaSmem mma; AttnSmem at; };

// ACT: 0 none, 1 relu, 2 tanh. OUTMAP: fp32 row m -> out + (m&127)*OUT_ROW + (m>>7)*BV
template <int ACT, bool HAS_BIAS, bool WF32, bool WBF, bool HAS_CIN, bool OUTMAP>
__device__ __forceinline__ void mma_body(
    MmaSmem& sm,
    const __nv_bfloat16* __restrict__ A, const __nv_bfloat16* __restrict__ W,
    const float* __restrict__ bias, const float* __restrict__ Cin,
    float* __restrict__ C, __nv_bfloat16* __restrict__ Cbf,
    int Nlog, int K, size_t ldc, int ldcin, int ldbf, int bm, int bn) {

    int tid = threadIdx.x;
    int wid = tid >> 5, lane = tid & 31;
    int wm = wid >> 1, wn = wid & 1;
    int g = lane >> 2, tg = lane & 3;

    int i0 = tid, i1 = tid + 256;
    int r0g = i0 >> 2, s0g = i0 & 3;
    int r1g = i1 >> 2, s1g = i1 & 3;
    const char* Ag0 = (const char*)(A + (size_t)(bm + r0g) * K + s0g * 8);
    const char* Ag1 = (const char*)(A + (size_t)(bm + r1g) * K + s1g * 8);
    const char* Wg0 = (const char*)(W + (size_t)(bn + r0g) * K + s0g * 8);
    const char* Wg1 = (const char*)(W + (size_t)(bn + r1g) * K + s1g * 8);
    uint32_t dA0 = (uint32_t)__cvta_generic_to_shared(&sm.sA[0][0]) + r0g * (PADR * 2) + s0g * 16;
    uint32_t dA1 = (uint32_t)__cvta_generic_to_shared(&sm.sA[0][0]) + r1g * (PADR * 2) + s1g * 16;
    uint32_t dB0 = (uint32_t)__cvta_generic_to_shared(&sm.sB[0][0]) + r0g * (PADR * 2) + s0g * 16;
    uint32_t dB1 = (uint32_t)__cvta_generic_to_shared(&sm.sB[0][0]) + r1g * (PADR * 2) + s1g * 16;

    float acc[2][8][4];
#pragma unroll
    for (int m = 0; m < 2; m++)
#pragma unroll
        for (int n = 0; n < 8; n++)
#pragma unroll
            for (int q = 0; q < 4; q++) acc[m][n][q] = 0.0f;

    {
        cpa16(dA0, Ag0); cpa16(dA1, Ag1);
        cpa16(dB0, Wg0); cpa16(dB1, Wg1);
        CP_COMMIT();
    }

    for (int k0 = 0; k0 < K; k0 += 32) {
        int cur = (k0 >> 5) & 1;
        if (k0 + 32 < K) {
            uint32_t off = (cur ^ 1) * (BUFW * 2);
            size_t kb = (size_t)(k0 + 32) * 2;
            cpa16(dA0 + off, Ag0 + kb); cpa16(dA1 + off, Ag1 + kb);
            cpa16(dB0 + off, Wg0 + kb); cpa16(dB1 + off, Wg1 + kb);
            CP_COMMIT();
            CP_WAIT1();
        } else {
            CP_WAIT0();
        }
        __syncthreads();
        const uint32_t* s32A = (const uint32_t*)sm.sA[cur];
        const uint32_t* s32B = (const uint32_t*)sm.sB[cur];
#pragma unroll
        for (int ks = 0; ks < 2; ks++) {
            int kb2 = ks * 8;
            uint32_t af[2][4];
#pragma unroll
            for (int m = 0; m < 2; m++) {
                int r = (wm * 32 + m * 16 + g) * 20;
                af[m][0] = s32A[r + kb2 + tg];
                af[m][1] = s32A[r + 160 + kb2 + tg];
                af[m][2] = s32A[r + kb2 + 4 + tg];
                af[m][3] = s32A[r + 160 + kb2 + 4 + tg];
            }
#pragma unroll
            for (int n = 0; n < 8; n++) {
                int rb = (wn * 64 + n * 8 + g) * 20;
                uint32_t bf0 = s32B[rb + kb2 + tg];
                uint32_t bf1 = s32B[rb + kb2 + 4 + tg];
                mma16816(acc[0][n], af[0], bf0, bf1);
                mma16816(acc[1][n], af[1], bf0, bf1);
            }
        }
        __syncthreads();
    }

#pragma unroll
    for (int m = 0; m < 2; m++) {
        int row0 = bm + wm * 32 + m * 16 + g;
#pragma unroll
        for (int n = 0; n < 8; n++) {
            int col = bn + wn * 64 + n * 8 + tg * 2;
            float v0 = acc[m][n][0], v1 = acc[m][n][1];
            float v2 = acc[m][n][2], v3 = acc[m][n][3];
            if (HAS_BIAS) {
                if (col < Nlog) { float bb = bias[col]; v0 += bb; v2 += bb; }
                if (col + 1 < Nlog) { float bb = bias[col + 1]; v1 += bb; v3 += bb; }
            }
            if (HAS_CIN) {
                if (col + 1 < Nlog) {
                    float2 c0 = *(const float2*)(Cin + (size_t)row0 * ldcin + col);
                    float2 c1 = *(const float2*)(Cin + (size_t)(row0 + 8) * ldcin + col);
                    v0 += c0.x; v1 += c0.y; v2 += c1.x; v3 += c1.y;
                } else if (col < Nlog) {
                    v0 += Cin[(size_t)row0 * ldcin + col];
                    v2 += Cin[(size_t)(row0 + 8) * ldcin + col];
                }
            }
            if (ACT == 1) {
                v0 = fmaxf(v0, 0.f); v1 = fmaxf(v1, 0.f);
                v2 = fmaxf(v2, 0.f); v3 = fmaxf(v3, 0.f);
            } else if (ACT == 2) {
                v0 = tanhf(v0); v1 = tanhf(v1); v2 = tanhf(v2); v3 = tanhf(v3);
            }
            if (WF32) {
                size_t ra, rb2;
                if (OUTMAP) {
                    ra = (size_t)(row0 & 127) * OUT_ROW + (size_t)(row0 >> 7) * BV;
                    rb2 = (size_t)((row0 + 8) & 127) * OUT_ROW + (size_t)((row0 + 8) >> 7) * BV;
                } else {
                    ra = (size_t)row0 * ldc;
                    rb2 = (size_t)(row0 + 8) * ldc;
                }
                if (col + 1 < Nlog) {
                    *(float2*)(C + ra + col) = make_float2(v0, v1);
                    *(float2*)(C + rb2 + col) = make_float2(v2, v3);
                } else if (col < Nlog) {
                    C[ra + col] = v0;
                    C[rb2 + col] = v2;
                }
            }
            if (WBF) {
                *(__nv_bfloat162*)(Cbf + (size_t)row0 * ldbf + col) =
                    __floats2bfloat162_rn(v0, v1);
                *(__nv_bfloat162*)(Cbf + (size_t)(row0 + 8) * ldbf + col) =
                    __floats2bfloat162_rn(v2, v3);
            }
        }
    }
}

template <int ACT, bool HAS_BIAS, bool WF32, bool WBF, bool HAS_CIN, bool OUTMAP>
__global__ void __launch_bounds__(256) gemm_mma(
    const __nv_bfloat16* __restrict__ A, const __nv_bfloat16* __restrict__ W,
    const float* __restrict__ bias, const float* __restrict__ Cin,
    float* __restrict__ C, __nv_bfloat16* __restrict__ Cbf,
    int Nlog, int K, size_t ldc, int ldcin, int ldbf) {
    __shared__ MmaSmem sm;
    mma_body<ACT, HAS_BIAS, WF32, WBF, HAS_CIN, OUTMAP>(
        sm, A, W, bias, Cin, C, Cbf, Nlog, K, ldc, ldcin, ldbf,
        blockIdx.x * 128, blockIdx.y * 128);
}

// ---------------- persistent step-loop mega-kernel ----------------
__global__ void __launch_bounds__(256) step_loop_kernel(
    const __nv_bfloat16* __restrict__ whh_bf, const float* __restrict__ gx,
    float* __restrict__ gates, float* __restrict__ h, float* __restrict__ c,
    __nv_bfloat16* __restrict__ h_bf, __nv_bfloat16* __restrict__ sent_bf,
    const __nv_bfloat16* __restrict__ seW_bf, const __nv_bfloat16* __restrict__ hoW_bf,
    const float* __restrict__ seb, const float* __restrict__ hob,
    float* __restrict__ sentemb, float* __restrict__ hemb,
    const __nv_bfloat16* __restrict__ vemb_bf, const float* __restrict__ alW,
    const float* __restrict__ alb, const __nv_bfloat16* __restrict__ v_bf,
    __nv_bfloat16* __restrict__ x2_bf,
    const __nv_bfloat16* __restrict__ a2hW_bf, const float* __restrict__ a2hb,
    __nv_bfloat16* __restrict__ hout_all) {
    __shared__ StepSmem smu;
    int blk = blockIdx.x;
    int tid = threadIdx.x;
    unsigned sense = 0;

    for (int t = 0; t < TT; t++) {
        // P1: gates = gx[t] + h@w_hh^T  (20 CTAs)
        if (blk < G5 / 128) {
            mma_body<0, false, true, false, true, false>(
                smu.mma, h_bf, whh_bf, nullptr, gx + (size_t)t * BB * G5, gates,
                nullptr, G5, RR, G5, G5, 0, 0, blk * 128);
        }
        sense ^= 1; gbar(sense);

        // P2: LSTM pointwise (all CTAs, 512 elems each)
        {
            int base = blk * 512 + tid;
#pragma unroll
            for (int u = 0; u < 2; u++) {
                int idx = base + u * 256;
                int b = idx >> 9, r = idx & 511;
                const float* gg = gates + (size_t)b * G5;
                float ig = sigmoidf_(gg[r]);
                float fg = sigmoidf_(gg[RR + r]);
                float g2 = tanhf(gg[2 * RR + r]);
                float og = sigmoidf_(gg[3 * RR + r]);
                float sg = sigmoidf_(gg[4 * RR + r]);
                float cy = tanhf(fg * c[idx] + ig * g2);
                c[idx] = cy;
                float hy = og * cy;
                h[idx] = hy;
                h_bf[idx] = __float2bfloat16(hy);
                sent_bf[idx] = __float2bfloat16(sg * cy);
            }
        }
        sense ^= 1; gbar(sense);

        // P3: se/ho GEMMs (8 CTAs)
        if (blk < 8) {
            if (blk < 4)
                mma_body<0, true, true, false, false, false>(
                    smu.mma, sent_bf, seW_bf, seb, nullptr, sentemb, nullptr,
                    HH, RR, HH, 0, 0, 0, blk * 128);
            else
                mma_body<0, true, true, false, false, false>(
                    smu.mma, h_bf, hoW_bf, hob, nullptr, hemb, nullptr,
                    HH, RR, HH, 0, 0, 0, (blk - 4) * 128);
        }
        sense ^= 1; gbar(sense);

        // P4: attention + cHat + (+hy) (128 CTAs, one per b)
        {
            int b = blk;
            float* sAl = smu.at.sAl;
            float* sH = smu.at.sH;
            float* sSc = smu.at.sSc;
            float* red = smu.at.red;
            for (int j = tid; j < HH; j += 256) {
                sAl[j] = alW[j];
                sH[j] = hemb[(size_t)b * HH + j];
            }
            __syncthreads();
            int warp = tid >> 5, lane = tid & 31;
            float ab = alb[0];
            for (int a = warp; a < A1; a += 8) {
                float s = 0.0f;
                if (a == 0) {
                    const float* e = sentemb + (size_t)b * HH;
                    for (int j = lane; j < HH; j += 32) s += sAl[j] * tanh_fast(e[j] + sH[j]);
                } else {
                    const __nv_bfloat16* e = vemb_bf + ((size_t)b * AA + (a - 1)) * HH;
                    for (int j = lane; j < HH; j += 32)
                        s += sAl[j] * tanh_fast(__bfloat162float(e[j]) + sH[j]);
                }
#pragma unroll
                for (int o = 16; o > 0; o >>= 1) s += __shfl_down_sync(0xffffffffu, s, o);
                if (lane == 0) sSc[a] = s + ab;
            }
            __syncthreads();
            float m = -INFINITY;
            for (int a = tid; a < A1; a += 256) m = fmaxf(m, sSc[a]);
            red[tid] = m; __syncthreads();
            for (int st = 128; st > 0; st >>= 1) {
                if (tid < st) red[tid] = fmaxf(red[tid], red[tid + st]);
                __syncthreads();
            }
            float mx = red[0]; __syncthreads();
            float sum = 0.0f;
            for (int a = tid; a < A1; a += 256) sum += expf(sSc[a] - mx);
            red[tid] = sum; __syncthreads();
            for (int st = 128; st > 0; st >>= 1) {
                if (tid < st) red[tid] += red[tid + st];
                __syncthreads();
            }
            float inv = 1.0f / red[0];
            __syncthreads();
            for (int a = tid; a < A1; a += 256) sSc[a] = expf(sSc[a] - mx) * inv;
            __syncthreads();
            const __nv_bfloat162* vp2 = (const __nv_bfloat162*)(v_bf + (size_t)b * AA * RR);
            __nv_bfloat162 sv = ((const __nv_bfloat162*)(sent_bf + (size_t)b * RR))[tid];
            float a0 = sSc[0];
            float acc0 = a0 * __low2float(sv);
            float acc1 = a0 * __high2float(sv);
            for (int a = 0; a < AA; a++) {
                __nv_bfloat162 vv = vp2[(size_t)a * (RR / 2) + tid];
                float s = sSc[a + 1];
                acc0 += s * __low2float(vv);
                acc1 += s * __high2float(vv);
            }
            float2 hv = *(const float2*)(h + (size_t)b * RR + 2 * tid);
            ((__nv_bfloat162*)(x2_bf + (size_t)b * RR))[tid] =
                __floats2bfloat162_rn(acc0 + hv.x, acc1 + hv.y);
        }
        sense ^= 1; gbar(sense);

        // P5: hout_all[t] = tanh(x2@a2hW^T + a2hb)  (4 CTAs, no trailing barrier:
        // output only read post-kernel; next P1 touches disjoint data)
        if (blk < 4) {
            mma_body<2, true, false, true, false, false>(
                smu.mma, x2_bf, a2hW_bf, a2hb, nullptr, nullptr,
                hout_all + (size_t)t * BB * RR, RR, RR, 0, 0, RR, 0, blk * 128);
        }
    }
}

// ---------------- conversions ----------------
__global__ void cvt_f2b4(const float* __restrict__ in, __nv_bfloat16* __restrict__ out, int n4) {
    int i = blockIdx.x * blockDim.x + threadIdx.x;
    if (i >= n4) return;
    float4 v = ((const float4*)in)[i];
    __nv_bfloat162* p = (__nv_bfloat162*)out + i * 2;
    p[0] = __floats2bfloat162_rn(v.x, v.y);
    p[1] = __floats2bfloat162_rn(v.z, v.w);
}
__global__ void pad_wih_bf(const float* __restrict__ w, __nv_bfloat16* __restrict__ wp) {
    int idx = blockIdx.x * blockDim.x + threadIdx.x;
    if (idx >= G5 * DPK) return;
    int r = idx / DPK, c = idx % DPK;
    wp[idx] = (c < DD) ? __float2bfloat16(w[r * DD + c]) : __float2bfloat16(0.0f);
}
__global__ void pad_lgw_bf(const float* __restrict__ w, __nv_bfloat16* __restrict__ wp) {
    int idx = blockIdx.x * blockDim.x + threadIdx.x;
    if (idx >= BVP * RR) return;
    int r = idx / RR, c = idx % RR;
    wp[idx] = (r < BV) ? __float2bfloat16(w[(size_t)r * RR + c]) : __float2bfloat16(0.0f);
}
__global__ void embed_all_bf(const int* __restrict__ seq, const float* __restrict__ E,
                             __nv_bfloat16* __restrict__ xall) {
    int idx = blockIdx.x * blockDim.x + threadIdx.x;
    if (idx >= TT * BB * DPK) return;
    int d = idx % DPK;
    int row = idx / DPK;
    int t = row / BB, b = row % BB;
    float v = 0.0f;
    if (d < DD) {
        int tok = seq[b * 21 + t];
        v = fmaxf(E[(size_t)tok * DD + d], 0.0f);
    }
    xall[idx] = __float2bfloat16(v);
}
__global__ void init_state_kernel(float* h, float* c, __nv_bfloat16* h_bf) {
    int i = blockIdx.x * blockDim.x + threadIdx.x;
    if (i < BB * RR) { h[i] = 0.0f; c[i] = 0.0f; h_bf[i] = __float2bfloat16(0.0f); }
}

// ---------------- batched log-softmax ----------------
__global__ void __launch_bounds__(256) logsm_all(float* __restrict__ out) {
    float* p = out + (size_t)blockIdx.x * OUT_ROW + (size_t)blockIdx.y * BV;
    __shared__ float red[256];
    int tid = threadIdx.x;
    float m = -INFINITY;
    for (int i = tid; i < BV; i += 256) m = fmaxf(m, p[i]);
    red[tid] = m; __syncthreads();
    for (int st = 128; st > 0; st >>= 1) {
        if (tid < st) red[tid] = fmaxf(red[tid], red[tid + st]);
        __syncthreads();
    }
    float mx = red[0]; __syncthreads();
    float sum = 0.0f;
    for (int i = tid; i < BV; i += 256) sum += expf(p[i] - mx);
    red[tid] = sum; __syncthreads();
    for (int st = 128; st > 0; st >>= 1) {
        if (tid < st) red[tid] += red[tid + st];
        __syncthreads();
    }
    float lse = mx + logf(red[0]);
    for (int i = tid; i < BV; i += 256) p[i] -= lse;
}

// ---------------- launch ----------------
extern "C" void kernel_launch(void* const* d_in, const int* in_sizes, int n_in,
                              void* d_out, int out_size) {
    const float* att  = (const float*)d_in[0];
    const int*   seq  = (const int*)d_in[1];
    const float* E    = (const float*)d_in[2];
    const float* w_ih = (const float*)d_in[3];
    const float* w_hh = (const float*)d_in[4];
    const float* aeW  = (const float*)d_in[5];
    const float* aeb  = (const float*)d_in[6];
    const float* c2aW = (const float*)d_in[7];
    const float* c2ab = (const float*)d_in[8];
    const float* seW  = (const float*)d_in[9];
    const float* seb  = (const float*)d_in[10];
    const float* hoW  = (const float*)d_in[11];
    const float* hob  = (const float*)d_in[12];
    const float* alW  = (const float*)d_in[13];
    const float* alb  = (const float*)d_in[14];
    const float* a2hW = (const float*)d_in[15];
    const float* a2hb = (const float*)d_in[16];
    const float* lgW  = (const float*)d_in[17];
    const float* lgb  = (const float*)d_in[18];
    float* out = (float*)d_out;

    __nv_bfloat16 *att_bf, *aeW_bf, *c2aW_bf, *whh_bf, *seW_bf, *hoW_bf, *a2hW_bf;
    __nv_bfloat16 *v_bf, *vemb_bf, *xall_bf, *wih_bf, *lgW_bf, *hout_all, *h_bf, *sent_bf, *x2_bf;
    float *gx, *gates, *h, *c, *sentemb, *hemb;
    cudaGetSymbolAddress((void**)&att_bf, g_att_bf);
    cudaGetSymbolAddress((void**)&aeW_bf, g_aeW_bf);
    cudaGetSymbolAddress((void**)&c2aW_bf, g_c2aW_bf);
    cudaGetSymbolAddress((void**)&whh_bf, g_whh_bf);
    cudaGetSymbolAddress((void**)&seW_bf, g_seW_bf);
    cudaGetSymbolAddress((void**)&hoW_bf, g_hoW_bf);
    cudaGetSymbolAddress((void**)&a2hW_bf, g_a2hW_bf);
    cudaGetSymbolAddress((void**)&v_bf, g_v_bf);
    cudaGetSymbolAddress((void**)&vemb_bf, g_vemb_bf);
    cudaGetSymbolAddress((void**)&xall_bf, g_xall_bf);
    cudaGetSymbolAddress((void**)&wih_bf, g_wih_bf);
    cudaGetSymbolAddress((void**)&lgW_bf, g_lgW_bf);
    cudaGetSymbolAddress((void**)&hout_all, g_hout_all);
    cudaGetSymbolAddress((void**)&h_bf, g_h_bf);
    cudaGetSymbolAddress((void**)&sent_bf, g_sent_bf);
    cudaGetSymbolAddress((void**)&x2_bf, g_x2_bf);
    cudaGetSymbolAddress((void**)&gx, g_gx);
    cudaGetSymbolAddress((void**)&gates, g_gates);
    cudaGetSymbolAddress((void**)&h, g_h);
    cudaGetSymbolAddress((void**)&c, g_c);
    cudaGetSymbolAddress((void**)&sentemb, g_sentemb);
    cudaGetSymbolAddress((void**)&hemb, g_hemb);

    // fork stream B off the (captured) default stream
    cudaEventRecord(s_evFork, 0);
    cudaStreamWaitEvent(s_b, s_evFork, 0);

    // Stream B: token path + logits weight prep + gx GEMM
    pad_wih_bf<<<(G5 * DPK + 255) / 256, 256, 0, s_b>>>(w_ih, wih_bf);
    embed_all_bf<<<(TT * BB * DPK + 255) / 256, 256, 0, s_b>>>(seq, E, xall_bf);
    pad_lgw_bf<<<(BVP * RR + 255) / 256, 256, 0, s_b>>>(lgW, lgW_bf);
    gemm_mma<0, false, true, false, false, false>
        <<<dim3(TT * BB / 128, G5 / 128), 256, 0, s_b>>>(
        xall_bf, wih_bf, nullptr, nullptr, gx, nullptr, G5, DPK, G5, 0, 0);
    cudaEventRecord(s_evGx, s_b);

    // Stream A: image path + weight conversions
    init_state_kernel<<<(BB * RR + 255) / 256, 256>>>(h, c, h_bf);
    cvt_f2b4<<<(MROWS * FEAT / 4 + 255) / 256, 256>>>(att, att_bf, MROWS * FEAT / 4);
    cvt_f2b4<<<(RR * FEAT / 4 + 255) / 256, 256>>>(aeW, aeW_bf, RR * FEAT / 4);
    cvt_f2b4<<<(RR * RR / 4 + 255) / 256, 256>>>(c2aW, c2aW_bf, RR * RR / 4);
    cvt_f2b4<<<(G5 * RR / 4 + 255) / 256, 256>>>(w_hh, whh_bf, G5 * RR / 4);
    cvt_f2b4<<<(HH * RR / 4 + 255) / 256, 256>>>(seW, seW_bf, HH * RR / 4);
    cvt_f2b4<<<(HH * RR / 4 + 255) / 256, 256>>>(hoW, hoW_bf, HH * RR / 4);
    cvt_f2b4<<<(RR * RR / 4 + 255) / 256, 256>>>(a2hW, a2hW_bf, RR * RR / 4);
    gemm_mma<1, true, false, true, false, false><<<dim3(MROWS / 128, RR / 128), 256>>>(
        att_bf, aeW_bf, aeb, nullptr, nullptr, v_bf, RR, FEAT, 0, 0, RR);
    gemm_mma<0, true, false, true, false, false><<<dim3(MROWS / 128, RR / 128), 256>>>(
        v_bf, c2aW_bf, c2ab, nullptr, nullptr, vemb_bf, RR, RR, 0, 0, RR);

    cudaStreamWaitEvent(0, s_evGx, 0);

    // Persistent recurrent loop (all 20 steps, one kernel)
    step_loop_kernel<<<GRIDP, 256>>>(
        whh_bf, gx, gates, h, c, h_bf, sent_bf, seW_bf, hoW_bf, seb, hob,
        sentemb, hemb, vemb_bf, alW, alb, v_bf, x2_bf, a2hW_bf, a2hb, hout_all);

    // Batched logits for all steps: [2560, BVP] with row->out mapping
    gemm_mma<0, true, true, false, false, true>
        <<<dim3(TT * BB / 128, BVP / 128), 256>>>(
        hout_all, lgW_bf, lgb, nullptr, out, nullptr, BV, RR, 0, 0, 0);
    // Batched log-softmax
    logsm_all<<<dim3(BB, TT), 256>>>(out);
}

// round 9
// speedup vs baseline: 6.1156x; 1.2320x over previous
#include <cuda_runtime.h>
#include <cuda_bf16.h>
#include <math.h>
#include <stddef.h>
#include <stdint.h>

// Problem dims
#define BV 7800
#define BVP 7808
#define DD 300
#define DPK 320
#define RR 512
#define HH 512
#define FEAT 2048
#define BB 128
#define AA 196
#define TT 20
#define A1 197
#define G5 2560
#define MROWS 25088
#define OUT_ROW 156000
#define GRIDP 128

// ---------------- device scratch ----------------
__device__ __nv_bfloat16 g_att_bf[MROWS * FEAT];
__device__ __nv_bfloat16 g_aeW_bf[RR * FEAT];
__device__ __nv_bfloat16 g_c2aW_bf[RR * RR];
__device__ __nv_bfloat16 g_whh_bf[G5 * RR];
__device__ __nv_bfloat16 g_seW_bf[HH * RR];
__device__ __nv_bfloat16 g_hoW_bf[HH * RR];
__device__ __nv_bfloat16 g_a2hW_bf[RR * RR];
__device__ __nv_bfloat16 g_v_bf[MROWS * RR];
__device__ __nv_bfloat16 g_vemb_bf[MROWS * RR];
__device__ __nv_bfloat16 g_xall_bf[TT * BB * DPK];
__device__ __nv_bfloat16 g_wih_bf[G5 * DPK];
__device__ __nv_bfloat16 g_lgW_bf[BVP * RR];
__device__ __nv_bfloat16 g_hout_all[TT * BB * RR];
__device__ __nv_bfloat16 g_h_bf[BB * RR];
__device__ __nv_bfloat16 g_sent_bf[BB * RR];
__device__ __nv_bfloat16 g_x2_bf[BB * RR];
__device__ float g_gx[TT * BB * G5];
__device__ float g_gates[BB * G5];
__device__ float g_h[BB * RR];
__device__ float g_c[BB * RR];
__device__ float g_sentemb[BB * HH];
__device__ float g_hemb[BB * HH];
__device__ unsigned g_bar_count = 0;
__device__ volatile unsigned g_bar_sense = 0;

// ---------------- static stream/event resources ----------------
static cudaStream_t s_b = nullptr;
static cudaEvent_t s_evFork = nullptr, s_evGx = nullptr;
static struct StreamInit {
    StreamInit() {
        cudaStreamCreateWithFlags(&s_b, cudaStreamNonBlocking);
        cudaEventCreateWithFlags(&s_evFork, cudaEventDisableTiming);
        cudaEventCreateWithFlags(&s_evGx, cudaEventDisableTiming);
    }
} s_streamInit;

// ---------------- helpers ----------------
__device__ __forceinline__ float sigmoidf_(float x) { return 1.0f / (1.0f + expf(-x)); }
__device__ __forceinline__ float tanh_fast(float x) {
    float y;
    asm("tanh.approx.f32 %0, %1;" : "=f"(y) : "f"(x));
    return y;
}
__device__ __forceinline__ void mma16816(float* c, const uint32_t* a, uint32_t b0, uint32_t b1) {
    asm volatile(
        "mma.sync.aligned.m16n8k16.row.col.f32.bf16.bf16.f32 "
        "{%0,%1,%2,%3}, {%4,%5,%6,%7}, {%8,%9}, {%0,%1,%2,%3};"
        : "+f"(c[0]), "+f"(c[1]), "+f"(c[2]), "+f"(c[3])
        : "r"(a[0]), "r"(a[1]), "r"(a[2]), "r"(a[3]), "r"(b0), "r"(b1));
}
__device__ __forceinline__ void cpa16(uint32_t dst, const void* src) {
    asm volatile("cp.async.cg.shared.global [%0], [%1], 16;" :: "r"(dst), "l"(src));
}
#define CP_COMMIT() asm volatile("cp.async.commit_group;" ::: "memory")
#define CP_WAIT1()  asm volatile("cp.async.wait_group 1;" ::: "memory")
#define CP_WAIT0()  asm volatile("cp.async.wait_group 0;" ::: "memory")

__device__ __forceinline__ void gbar(unsigned sense) {
    __syncthreads();
    if (threadIdx.x == 0) {
        __threadfence();
        unsigned arrived = atomicAdd(&g_bar_count, 1u);
        if (arrived == GRIDP - 1) {
            g_bar_count = 0;
            __threadfence();
            g_bar_sense = sense;
        } else {
            while (g_bar_sense != sense) __nanosleep(64);
        }
        __threadfence();
    }
    __syncthreads();
}

// ---------------- bf16 mma.sync GEMM (generic, static smem) ----------------
#define PADR 40
#define BUFW (128 * PADR)
struct MmaSmem { __nv_bfloat16 sA[2][BUFW]; __nv_bfloat16 sB[2][BUFW]; };

template <int ACT, bool HAS_BIAS, bool WF32, bool WBF, bool HAS_CIN, bool OUTMAP>
__device__ __forceinline__ void mma_body(
    MmaSmem& sm,
    const __nv_bfloat16* __restrict__ A, const __nv_bfloat16* __restrict__ W,
    const float* __restrict__ bias, const float* __restrict__ Cin,
    float* __restrict__ C, __nv_bfloat16* __restrict__ Cbf,
    int Nlog, int K, size_t ldc, int ldcin, int ldbf, int bm, int bn) {

    int tid = threadIdx.x;
    int wid = tid >> 5, lane = tid & 31;
    int wm = wid >> 1, wn = wid & 1;
    int g = lane >> 2, tg = lane & 3;

    int r0g = tid >> 2, s0g = tid & 3;
    int r1g = (tid + 256) >> 2, s1g = tid & 3;
    const char* Ag0 = (const char*)(A + (size_t)(bm + r0g) * K + s0g * 8);
    const char* Ag1 = (const char*)(A + (size_t)(bm + r1g) * K + s1g * 8);
    const char* Wg0 = (const char*)(W + (size_t)(bn + r0g) * K + s0g * 8);
    const char* Wg1 = (const char*)(W + (size_t)(bn + r1g) * K + s1g * 8);
    uint32_t dA0 = (uint32_t)__cvta_generic_to_shared(&sm.sA[0][0]) + r0g * (PADR * 2) + s0g * 16;
    uint32_t dA1 = (uint32_t)__cvta_generic_to_shared(&sm.sA[0][0]) + r1g * (PADR * 2) + s1g * 16;
    uint32_t dB0 = (uint32_t)__cvta_generic_to_shared(&sm.sB[0][0]) + r0g * (PADR * 2) + s0g * 16;
    uint32_t dB1 = (uint32_t)__cvta_generic_to_shared(&sm.sB[0][0]) + r1g * (PADR * 2) + s1g * 16;

    float acc[2][8][4];
#pragma unroll
    for (int m = 0; m < 2; m++)
#pragma unroll
        for (int n = 0; n < 8; n++)
#pragma unroll
            for (int q = 0; q < 4; q++) acc[m][n][q] = 0.0f;

    cpa16(dA0, Ag0); cpa16(dA1, Ag1);
    cpa16(dB0, Wg0); cpa16(dB1, Wg1);
    CP_COMMIT();

    for (int k0 = 0; k0 < K; k0 += 32) {
        int cur = (k0 >> 5) & 1;
        if (k0 + 32 < K) {
            uint32_t off = (cur ^ 1) * (BUFW * 2);
            size_t kb = (size_t)(k0 + 32) * 2;
            cpa16(dA0 + off, Ag0 + kb); cpa16(dA1 + off, Ag1 + kb);
            cpa16(dB0 + off, Wg0 + kb); cpa16(dB1 + off, Wg1 + kb);
            CP_COMMIT();
            CP_WAIT1();
        } else {
            CP_WAIT0();
        }
        __syncthreads();
        const uint32_t* s32A = (const uint32_t*)sm.sA[cur];
        const uint32_t* s32B = (const uint32_t*)sm.sB[cur];
#pragma unroll
        for (int ks = 0; ks < 2; ks++) {
            int kb2 = ks * 8;
            uint32_t af[2][4];
#pragma unroll
            for (int m = 0; m < 2; m++) {
                int r = (wm * 32 + m * 16 + g) * 20;
                af[m][0] = s32A[r + kb2 + tg];
                af[m][1] = s32A[r + 160 + kb2 + tg];
                af[m][2] = s32A[r + kb2 + 4 + tg];
                af[m][3] = s32A[r + 160 + kb2 + 4 + tg];
            }
#pragma unroll
            for (int n = 0; n < 8; n++) {
                int rb = (wn * 64 + n * 8 + g) * 20;
                uint32_t bf0 = s32B[rb + kb2 + tg];
                uint32_t bf1 = s32B[rb + kb2 + 4 + tg];
                mma16816(acc[0][n], af[0], bf0, bf1);
                mma16816(acc[1][n], af[1], bf0, bf1);
            }
        }
        __syncthreads();
    }

#pragma unroll
    for (int m = 0; m < 2; m++) {
        int row0 = bm + wm * 32 + m * 16 + g;
#pragma unroll
        for (int n = 0; n < 8; n++) {
            int col = bn + wn * 64 + n * 8 + tg * 2;
            float v0 = acc[m][n][0], v1 = acc[m][n][1];
            float v2 = acc[m][n][2], v3 = acc[m][n][3];
            if (HAS_BIAS) {
                if (col < Nlog) { float bb = bias[col]; v0 += bb; v2 += bb; }
                if (col + 1 < Nlog) { float bb = bias[col + 1]; v1 += bb; v3 += bb; }
            }
            if (HAS_CIN) {
                float2 c0 = *(const float2*)(Cin + (size_t)row0 * ldcin + col);
                float2 c1 = *(const float2*)(Cin + (size_t)(row0 + 8) * ldcin + col);
                v0 += c0.x; v1 += c0.y; v2 += c1.x; v3 += c1.y;
            }
            if (ACT == 1) {
                v0 = fmaxf(v0, 0.f); v1 = fmaxf(v1, 0.f);
                v2 = fmaxf(v2, 0.f); v3 = fmaxf(v3, 0.f);
            } else if (ACT == 2) {
                v0 = tanhf(v0); v1 = tanhf(v1); v2 = tanhf(v2); v3 = tanhf(v3);
            }
            if (WF32) {
                size_t ra, rb2;
                if (OUTMAP) {
                    ra = (size_t)(row0 & 127) * OUT_ROW + (size_t)(row0 >> 7) * BV;
                    rb2 = (size_t)((row0 + 8) & 127) * OUT_ROW + (size_t)((row0 + 8) >> 7) * BV;
                } else {
                    ra = (size_t)row0 * ldc;
                    rb2 = (size_t)(row0 + 8) * ldc;
                }
                if (col + 1 < Nlog) {
                    *(float2*)(C + ra + col) = make_float2(v0, v1);
                    *(float2*)(C + rb2 + col) = make_float2(v2, v3);
                } else if (col < Nlog) {
                    C[ra + col] = v0;
                    C[rb2 + col] = v2;
                }
            }
            if (WBF) {
                *(__nv_bfloat162*)(Cbf + (size_t)row0 * ldbf + col) =
                    __floats2bfloat162_rn(v0, v1);
                *(__nv_bfloat162*)(Cbf + (size_t)(row0 + 8) * ldbf + col) =
                    __floats2bfloat162_rn(v2, v3);
            }
        }
    }
}

template <int ACT, bool HAS_BIAS, bool WF32, bool WBF, bool HAS_CIN, bool OUTMAP>
__global__ void __launch_bounds__(256) gemm_mma(
    const __nv_bfloat16* __restrict__ A, const __nv_bfloat16* __restrict__ W,
    const float* __restrict__ bias, const float* __restrict__ Cin,
    float* __restrict__ C, __nv_bfloat16* __restrict__ Cbf,
    int Nlog, int K, size_t ldc, int ldcin, int ldbf) {
    __shared__ MmaSmem sm;
    mma_body<ACT, HAS_BIAS, WF32, WBF, HAS_CIN, OUTMAP>(
        sm, A, W, bias, Cin, C, Cbf, Nlog, K, ldc, ldcin, ldbf,
        blockIdx.x * 128, blockIdx.y * 128);
}

// ---------------- resident-B GEMM: 128x128 tile, K=512, B in persistent smem ----------
// sB layout: 128 rows x 520 bf16 (260 b32 stride); A streamed via 2-stage cp.async.
#define BROW 520
template <int ACT, bool HAS_BIAS, bool WF32, bool WBF, bool HAS_CIN>
__device__ __forceinline__ void mma_resB(
    const __nv_bfloat16* __restrict__ sB, __nv_bfloat16* __restrict__ sAb,
    const __nv_bfloat16* __restrict__ A,
    const float* __restrict__ bias, const float* __restrict__ Cin,
    float* __restrict__ C, __nv_bfloat16* __restrict__ Cbf,
    size_t ldc, int ldcin, int ldbf, int bn) {

    int tid = threadIdx.x;
    int wid = tid >> 5, lane = tid & 31;
    int wm = wid >> 1, wn = wid & 1;
    int g = lane >> 2, tg = lane & 3;

    int r0g = tid >> 2, s0g = tid & 3;
    const char* Ag0 = (const char*)(A + (size_t)r0g * RR + s0g * 8);
    const char* Ag1 = (const char*)(A + (size_t)(r0g + 64) * RR + s0g * 8);
    uint32_t ab = (uint32_t)__cvta_generic_to_shared(sAb);
    uint32_t dA0 = ab + r0g * (PADR * 2) + s0g * 16;
    uint32_t dA1 = ab + (r0g + 64) * (PADR * 2) + s0g * 16;

    float acc[2][8][4];
#pragma unroll
    for (int m = 0; m < 2; m++)
#pragma unroll
        for (int n = 0; n < 8; n++)
#pragma unroll
            for (int q = 0; q < 4; q++) acc[m][n][q] = 0.0f;

    cpa16(dA0, Ag0); cpa16(dA1, Ag1);
    CP_COMMIT();
    const uint32_t* s32B = (const uint32_t*)sB;

    for (int k0 = 0; k0 < RR; k0 += 32) {
        int cur = (k0 >> 5) & 1;
        if (k0 + 32 < RR) {
            uint32_t off = (cur ^ 1) * (BUFW * 2);
            size_t kb = (size_t)(k0 + 32) * 2;
            cpa16(dA0 + off, Ag0 + kb); cpa16(dA1 + off, Ag1 + kb);
            CP_COMMIT();
            CP_WAIT1();
        } else {
            CP_WAIT0();
        }
        __syncthreads();
        const uint32_t* s32A = (const uint32_t*)(sAb + cur * BUFW);
        int kcol = k0 >> 1;
#pragma unroll
        for (int ks = 0; ks < 2; ks++) {
            int kb2 = ks * 8;
            uint32_t af[2][4];
#pragma unroll
            for (int m = 0; m < 2; m++) {
                int r = (wm * 32 + m * 16 + g) * 20;
                af[m][0] = s32A[r + kb2 + tg];
                af[m][1] = s32A[r + 160 + kb2 + tg];
                af[m][2] = s32A[r + kb2 + 4 + tg];
                af[m][3] = s32A[r + 160 + kb2 + 4 + tg];
            }
#pragma unroll
            for (int n = 0; n < 8; n++) {
                int rb = (wn * 64 + n * 8 + g) * 260 + kcol;
                uint32_t bf0 = s32B[rb + kb2 + tg];
                uint32_t bf1 = s32B[rb + kb2 + 4 + tg];
                mma16816(acc[0][n], af[0], bf0, bf1);
                mma16816(acc[1][n], af[1], bf0, bf1);
            }
        }
        __syncthreads();
    }

#pragma unroll
    for (int m = 0; m < 2; m++) {
        int row0 = wm * 32 + m * 16 + g;
#pragma unroll
        for (int n = 0; n < 8; n++) {
            int col = bn + wn * 64 + n * 8 + tg * 2;
            float v0 = acc[m][n][0], v1 = acc[m][n][1];
            float v2 = acc[m][n][2], v3 = acc[m][n][3];
            if (HAS_BIAS) {
                float b0 = bias[col], b1 = bias[col + 1];
                v0 += b0; v1 += b1; v2 += b0; v3 += b1;
            }
            if (HAS_CIN) {
                float2 c0 = *(const float2*)(Cin + (size_t)row0 * ldcin + col);
                float2 c1 = *(const float2*)(Cin + (size_t)(row0 + 8) * ldcin + col);
                v0 += c0.x; v1 += c0.y; v2 += c1.x; v3 += c1.y;
            }
            if (ACT == 2) { v0 = tanhf(v0); v1 = tanhf(v1); v2 = tanhf(v2); v3 = tanhf(v3); }
            if (WF32) {
                *(float2*)(C + (size_t)row0 * ldc + col) = make_float2(v0, v1);
                *(float2*)(C + (size_t)(row0 + 8) * ldc + col) = make_float2(v2, v3);
            }
            if (WBF) {
                *(__nv_bfloat162*)(Cbf + (size_t)row0 * ldbf + col) =
                    __floats2bfloat162_rn(v0, v1);
                *(__nv_bfloat162*)(Cbf + (size_t)(row0 + 8) * ldbf + col) =
                    __floats2bfloat162_rn(v2, v3);
            }
        }
    }
}

// ---------------- persistent step-loop, weights resident in smem ----------------
// dyn smem: [Bres 128x520 bf16 = 133120 B][Abuf 2xBUFW bf16 = 20480 B (attn overlay)]
#define SM_BRES 133120
#define SM_STEP (SM_BRES + 2 * BUFW * 2)
struct AttnSmem { float sAl[HH]; float sH[HH]; float sSc[224]; float red[256]; };

__global__ void __launch_bounds__(256) step_loop_kernel(
    const __nv_bfloat16* __restrict__ whh_bf, const float* __restrict__ gx,
    float* __restrict__ gates, float* __restrict__ h, float* __restrict__ c,
    __nv_bfloat16* __restrict__ h_bf, __nv_bfloat16* __restrict__ sent_bf,
    const __nv_bfloat16* __restrict__ seW_bf, const __nv_bfloat16* __restrict__ hoW_bf,
    const float* __restrict__ seb, const float* __restrict__ hob,
    float* __restrict__ sentemb, float* __restrict__ hemb,
    const __nv_bfloat16* __restrict__ vemb_bf, const float* __restrict__ alW,
    const float* __restrict__ alb, const __nv_bfloat16* __restrict__ v_bf,
    __nv_bfloat16* __restrict__ x2_bf,
    const __nv_bfloat16* __restrict__ a2hW_bf, const float* __restrict__ a2hb,
    __nv_bfloat16* __restrict__ hout_all) {
    extern __shared__ char dsm[];
    __nv_bfloat16* sB = (__nv_bfloat16*)dsm;
    __nv_bfloat16* sAb = (__nv_bfloat16*)(dsm + SM_BRES);
    AttnSmem* at = (AttnSmem*)(dsm + SM_BRES);

    int blk = blockIdx.x;
    int tid = threadIdx.x;
    unsigned sense = 0;

    // preload this CTA's resident weight slice (roles: 0-19 whh, 20-23 se, 24-27 ho, 28-31 a2h)
    const __nv_bfloat16* myW = nullptr;
    if (blk < 20) myW = whh_bf + (size_t)blk * 128 * RR;
    else if (blk < 24) myW = seW_bf + (size_t)(blk - 20) * 128 * RR;
    else if (blk < 28) myW = hoW_bf + (size_t)(blk - 24) * 128 * RR;
    else if (blk < 32) myW = a2hW_bf + (size_t)(blk - 28) * 128 * RR;
    if (myW) {
        const uint4* src = (const uint4*)myW;
        for (int i = tid; i < 128 * 64; i += 256) {
            int r = i >> 6, cq = i & 63;
            ((uint4*)(sB + (size_t)r * BROW))[cq] = src[r * 64 + cq];
        }
    }
    __syncthreads();

    // P1 for t=0
    if (blk < 20)
        mma_resB<0, false, true, false, true>(sB, sAb, h_bf, nullptr, gx, gates,
                                              nullptr, G5, G5, 0, blk * 128);
    sense ^= 1; gbar(sense);

    for (int t = 0; t < TT; t++) {
        // P2: LSTM pointwise
        {
            int base = blk * 512 + tid;
#pragma unroll
            for (int u = 0; u < 2; u++) {
                int idx = base + u * 256;
                int b = idx >> 9, r = idx & 511;
                const float* gg = gates + (size_t)b * G5;
                float ig = sigmoidf_(gg[r]);
                float fg = sigmoidf_(gg[RR + r]);
                float g2 = tanhf(gg[2 * RR + r]);
                float og = sigmoidf_(gg[3 * RR + r]);
                float sg = sigmoidf_(gg[4 * RR + r]);
                float cy = tanhf(fg * c[idx] + ig * g2);
                c[idx] = cy;
                float hy = og * cy;
                h[idx] = hy;
                h_bf[idx] = __float2bfloat16(hy);
                sent_bf[idx] = __float2bfloat16(sg * cy);
            }
        }
        sense ^= 1; gbar(sense);

        // P3: se/ho GEMMs on weight-resident CTAs 20-27
        if (blk >= 20 && blk < 24)
            mma_resB<0, true, true, false, false>(sB, sAb, sent_bf, seb, nullptr,
                                                  sentemb, nullptr, HH, 0, 0,
                                                  (blk - 20) * 128);
        else if (blk >= 24 && blk < 28)
            mma_resB<0, true, true, false, false>(sB, sAb, h_bf, hob, nullptr,
                                                  hemb, nullptr, HH, 0, 0,
                                                  (blk - 24) * 128);
        sense ^= 1; gbar(sense);

        // P4: attention + cHat + (+hy), all CTAs (one per b)
        {
            int b = blk;
            float* sAl = at->sAl;
            float* sH = at->sH;
            float* sSc = at->sSc;
            float* red = at->red;
            for (int j = tid; j < HH; j += 256) {
                sAl[j] = alW[j];
                sH[j] = hemb[(size_t)b * HH + j];
            }
            __syncthreads();
            int warp = tid >> 5, lane = tid & 31;
            float ab = alb[0];
            for (int a = warp; a < A1; a += 8) {
                float s = 0.0f;
                if (a == 0) {
                    const float* e = sentemb + (size_t)b * HH;
                    for (int j = lane; j < HH; j += 32) s += sAl[j] * tanh_fast(e[j] + sH[j]);
                } else {
                    const __nv_bfloat16* e = vemb_bf + ((size_t)b * AA + (a - 1)) * HH;
                    for (int j = lane; j < HH; j += 32)
                        s += sAl[j] * tanh_fast(__bfloat162float(e[j]) + sH[j]);
                }
#pragma unroll
                for (int o = 16; o > 0; o >>= 1) s += __shfl_down_sync(0xffffffffu, s, o);
                if (lane == 0) sSc[a] = s + ab;
            }
            __syncthreads();
            float m = -INFINITY;
            for (int a = tid; a < A1; a += 256) m = fmaxf(m, sSc[a]);
            red[tid] = m; __syncthreads();
            for (int st = 128; st > 0; st >>= 1) {
                if (tid < st) red[tid] = fmaxf(red[tid], red[tid + st]);
                __syncthreads();
            }
            float mx = red[0]; __syncthreads();
            float sum = 0.0f;
            for (int a = tid; a < A1; a += 256) sum += expf(sSc[a] - mx);
            red[tid] = sum; __syncthreads();
            for (int st = 128; st > 0; st >>= 1) {
                if (tid < st) red[tid] += red[tid + st];
                __syncthreads();
            }
            float inv = 1.0f / red[0];
            __syncthreads();
            for (int a = tid; a < A1; a += 256) sSc[a] = expf(sSc[a] - mx) * inv;
            __syncthreads();
            const __nv_bfloat162* vp2 = (const __nv_bfloat162*)(v_bf + (size_t)b * AA * RR);
            __nv_bfloat162 sv = ((const __nv_bfloat162*)(sent_bf + (size_t)b * RR))[tid];
            float a0 = sSc[0];
            float acc0 = a0 * __low2float(sv);
            float acc1 = a0 * __high2float(sv);
            for (int a = 0; a < AA; a++) {
                __nv_bfloat162 vv = vp2[(size_t)a * (RR / 2) + tid];
                float s = sSc[a + 1];
                acc0 += s * __low2float(vv);
                acc1 += s * __high2float(vv);
            }
            float2 hv = *(const float2*)(h + (size_t)b * RR + 2 * tid);
            ((__nv_bfloat162*)(x2_bf + (size_t)b * RR))[tid] =
                __floats2bfloat162_rn(acc0 + hv.x, acc1 + hv.y);
            __syncthreads();   // attn smem reuse safety before next GEMM overlays it
        }
        sense ^= 1; gbar(sense);

        // P5: hout_all[t] (CTAs 28-31)  ∥  P1 for t+1 (CTAs 0-19)
        if (blk >= 28 && blk < 32)
            mma_resB<2, true, false, true, false>(sB, sAb, x2_bf, a2hb, nullptr,
                                                  nullptr, hout_all + (size_t)t * BB * RR,
                                                  0, 0, RR, (blk - 28) * 128);
        else if (blk < 20 && t + 1 < TT)
            mma_resB<0, false, true, false, true>(sB, sAb, h_bf, nullptr,
                                                  gx + (size_t)(t + 1) * BB * G5, gates,
                                                  nullptr, G5, G5, 0, blk * 128);
        sense ^= 1; gbar(sense);
    }
    sense ^= 1; gbar(sense);  // 82nd barrier: even count -> sense state replay-safe
}

// ---------------- conversions ----------------
__global__ void cvt_f2b4(const float* __restrict__ in, __nv_bfloat16* __restrict__ out, int n4) {
    int i = blockIdx.x * blockDim.x + threadIdx.x;
    if (i >= n4) return;
    float4 v = ((const float4*)in)[i];
    __nv_bfloat162* p = (__nv_bfloat162*)out + i * 2;
    p[0] = __floats2bfloat162_rn(v.x, v.y);
    p[1] = __floats2bfloat162_rn(v.z, v.w);
}
__global__ void pad_wih_bf(const float* __restrict__ w, __nv_bfloat16* __restrict__ wp) {
    int idx = blockIdx.x * blockDim.x + threadIdx.x;
    if (idx >= G5 * DPK) return;
    int r = idx / DPK, c = idx % DPK;
    wp[idx] = (c < DD) ? __float2bfloat16(w[r * DD + c]) : __float2bfloat16(0.0f);
}
__global__ void pad_lgw_bf(const float* __restrict__ w, __nv_bfloat16* __restrict__ wp) {
    int idx = blockIdx.x * blockDim.x + threadIdx.x;
    if (idx >= BVP * RR) return;
    int r = idx / RR, c = idx % RR;
    wp[idx] = (r < BV) ? __float2bfloat16(w[(size_t)r * RR + c]) : __float2bfloat16(0.0f);
}
__global__ void embed_all_bf(const int* __restrict__ seq, const float* __restrict__ E,
                             __nv_bfloat16* __restrict__ xall) {
    int idx = blockIdx.x * blockDim.x + threadIdx.x;
    if (idx >= TT * BB * DPK) return;
    int d = idx % DPK;
    int row = idx / DPK;
    int t = row / BB, b = row % BB;
    float v = 0.0f;
    if (d < DD) {
        int tok = seq[b * 21 + t];
        v = fmaxf(E[(size_t)tok * DD + d], 0.0f);
    }
    xall[idx] = __float2bfloat16(v);
}
__global__ void init_state_kernel(float* h, float* c, __nv_bfloat16* h_bf) {
    int i = blockIdx.x * blockDim.x + threadIdx.x;
    if (i < BB * RR) { h[i] = 0.0f; c[i] = 0.0f; h_bf[i] = __float2bfloat16(0.0f); }
}

// ---------------- batched log-softmax ----------------
__global__ void __launch_bounds__(256) logsm_all(float* __restrict__ out) {
    float* p = out + (size_t)blockIdx.x * OUT_ROW + (size_t)blockIdx.y * BV;
    __shared__ float red[256];
    int tid = threadIdx.x;
    float m = -INFINITY;
    for (int i = tid; i < BV; i += 256) m = fmaxf(m, p[i]);
    red[tid] = m; __syncthreads();
    for (int st = 128; st > 0; st >>= 1) {
        if (tid < st) red[tid] = fmaxf(red[tid], red[tid + st]);
        __syncthreads();
    }
    float mx = red[0]; __syncthreads();
    float sum = 0.0f;
    for (int i = tid; i < BV; i += 256) sum += expf(p[i] - mx);
    red[tid] = sum; __syncthreads();
    for (int st = 128; st > 0; st >>= 1) {
        if (tid < st) red[tid] += red[tid + st];
        __syncthreads();
    }
    float lse = mx + logf(red[0]);
    for (int i = tid; i < BV; i += 256) p[i] -= lse;
}

// ---------------- launch ----------------
extern "C" void kernel_launch(void* const* d_in, const int* in_sizes, int n_in,
                              void* d_out, int out_size) {
    const float* att  = (const float*)d_in[0];
    const int*   seq  = (const int*)d_in[1];
    const float* E    = (const float*)d_in[2];
    const float* w_ih = (const float*)d_in[3];
    const float* w_hh = (const float*)d_in[4];
    const float* aeW  = (const float*)d_in[5];
    const float* aeb  = (const float*)d_in[6];
    const float* c2aW = (const float*)d_in[7];
    const float* c2ab = (const float*)d_in[8];
    const float* seW  = (const float*)d_in[9];
    const float* seb  = (const float*)d_in[10];
    const float* hoW  = (const float*)d_in[11];
    const float* hob  = (const float*)d_in[12];
    const float* alW  = (const float*)d_in[13];
    const float* alb  = (const float*)d_in[14];
    const float* a2hW = (const float*)d_in[15];
    const float* a2hb = (const float*)d_in[16];
    const float* lgW  = (const float*)d_in[17];
    const float* lgb  = (const float*)d_in[18];
    float* out = (float*)d_out;

    __nv_bfloat16 *att_bf, *aeW_bf, *c2aW_bf, *whh_bf, *seW_bf, *hoW_bf, *a2hW_bf;
    __nv_bfloat16 *v_bf, *vemb_bf, *xall_bf, *wih_bf, *lgW_bf, *hout_all, *h_bf, *sent_bf, *x2_bf;
    float *gx, *gates, *h, *c, *sentemb, *hemb;
    cudaGetSymbolAddress((void**)&att_bf, g_att_bf);
    cudaGetSymbolAddress((void**)&aeW_bf, g_aeW_bf);
    cudaGetSymbolAddress((void**)&c2aW_bf, g_c2aW_bf);
    cudaGetSymbolAddress((void**)&whh_bf, g_whh_bf);
    cudaGetSymbolAddress((void**)&seW_bf, g_seW_bf);
    cudaGetSymbolAddress((void**)&hoW_bf, g_hoW_bf);
    cudaGetSymbolAddress((void**)&a2hW_bf, g_a2hW_bf);
    cudaGetSymbolAddress((void**)&v_bf, g_v_bf);
    cudaGetSymbolAddress((void**)&vemb_bf, g_vemb_bf);
    cudaGetSymbolAddress((void**)&xall_bf, g_xall_bf);
    cudaGetSymbolAddress((void**)&wih_bf, g_wih_bf);
    cudaGetSymbolAddress((void**)&lgW_bf, g_lgW_bf);
    cudaGetSymbolAddress((void**)&hout_all, g_hout_all);
    cudaGetSymbolAddress((void**)&h_bf, g_h_bf);
    cudaGetSymbolAddress((void**)&sent_bf, g_sent_bf);
    cudaGetSymbolAddress((void**)&x2_bf, g_x2_bf);
    cudaGetSymbolAddress((void**)&gx, g_gx);
    cudaGetSymbolAddress((void**)&gates, g_gates);
    cudaGetSymbolAddress((void**)&h, g_h);
    cudaGetSymbolAddress((void**)&c, g_c);
    cudaGetSymbolAddress((void**)&sentemb, g_sentemb);
    cudaGetSymbolAddress((void**)&hemb, g_hemb);

    cudaFuncSetAttribute(step_loop_kernel,
                         cudaFuncAttributeMaxDynamicSharedMemorySize, SM_STEP);

    // fork stream B
    cudaEventRecord(s_evFork, 0);
    cudaStreamWaitEvent(s_b, s_evFork, 0);

    // Stream B: token path + logits weight prep + gx GEMM
    pad_wih_bf<<<(G5 * DPK + 255) / 256, 256, 0, s_b>>>(w_ih, wih_bf);
    embed_all_bf<<<(TT * BB * DPK + 255) / 256, 256, 0, s_b>>>(seq, E, xall_bf);
    pad_lgw_bf<<<(BVP * RR + 255) / 256, 256, 0, s_b>>>(lgW, lgW_bf);
    gemm_mma<0, false, true, false, false, false>
        <<<dim3(TT * BB / 128, G5 / 128), 256, 0, s_b>>>(
        xall_bf, wih_bf, nullptr, nullptr, gx, nullptr, G5, DPK, G5, 0, 0);
    cudaEventRecord(s_evGx, s_b);

    // Stream A: image path + weight conversions
    init_state_kernel<<<(BB * RR + 255) / 256, 256>>>(h, c, h_bf);
    cvt_f2b4<<<(MROWS * FEAT / 4 + 255) / 256, 256>>>(att, att_bf, MROWS * FEAT / 4);
    cvt_f2b4<<<(RR * FEAT / 4 + 255) / 256, 256>>>(aeW, aeW_bf, RR * FEAT / 4);
    cvt_f2b4<<<(RR * RR / 4 + 255) / 256, 256>>>(c2aW, c2aW_bf, RR * RR / 4);
    cvt_f2b4<<<(G5 * RR / 4 + 255) / 256, 256>>>(w_hh, whh_bf, G5 * RR / 4);
    cvt_f2b4<<<(HH * RR / 4 + 255) / 256, 256>>>(seW, seW_bf, HH * RR / 4);
    cvt_f2b4<<<(HH * RR / 4 + 255) / 256, 256>>>(hoW, hoW_bf, HH * RR / 4);
    cvt_f2b4<<<(RR * RR / 4 + 255) / 256, 256>>>(a2hW, a2hW_bf, RR * RR / 4);
    gemm_mma<1, true, false, true, false, false><<<dim3(MROWS / 128, RR / 128), 256>>>(
        att_bf, aeW_bf, aeb, nullptr, nullptr, v_bf, RR, FEAT, 0, 0, RR);
    gemm_mma<0, true, false, true, false, false><<<dim3(MROWS / 128, RR / 128), 256>>>(
        v_bf, c2aW_bf, c2ab, nullptr, nullptr, vemb_bf, RR, RR, 0, 0, RR);

    cudaStreamWaitEvent(0, s_evGx, 0);

    // Persistent recurrent loop, weights resident in smem
    step_loop_kernel<<<GRIDP, 256, SM_STEP>>>(
        whh_bf, gx, gates, h, c, h_bf, sent_bf, seW_bf, hoW_bf, seb, hob,
        sentemb, hemb, vemb_bf, alW, alb, v_bf, x2_bf, a2hW_bf, a2hb, hout_all);

    // Batched logits for all steps + batched log-softmax
    gemm_mma<0, true, true, false, false, true>
        <<<dim3(TT * BB / 128, BVP / 128), 256>>>(
        hout_all, lgW_bf, lgb, nullptr, out, nullptr, BV, RR, 0, 0, 0);
    logsm_all<<<dim3(BB, TT), 256>>>(out);
}